// round 14
// baseline (speedup 1.0000x reference)
#include <cuda_runtime.h>
#include <cuda_fp16.h>
#include <math.h>
#include <stdint.h>

// Problem constants
#define BB   32
#define SS   512
#define DD   512
#define HH   8
#define DKK  64
#define FFD  2048
#define NBLK 2
#define MTOK (BB*SS)            // 16384 token rows
#define BSD  (BB*SS*DD)         // 8388608
#define BSF  (BB*SS*FFD)        // 33554432

// Scratch (static device globals — no allocation allowed)
__device__ float  g_x[BSD];          // residual stream (fp32)
__device__ float  g_t[BSD];          // fp32 temp (proj / ffn out)
__device__ __half g_qh[BSD];         // q (fp16, attn input)
__device__ __half g_vh[BSD];         // v (fp16, attn input)
__device__ __half g_xh[BSD];         // fp16 activations
__device__ __half g_yh[BSD];
__device__ __half g_ah[BSD];         // attn output (fp16)
__device__ __half g_fh[BSF];         // ffn hidden (fp16)
__device__ __half g_wkt[NBLK*DD*DD]; // transposed fp16 weights [N][K]
__device__ __half g_wvt[NBLK*DD*DD];
__device__ __half g_wot[NBLK*DD*DD];
__device__ __half g_w1t[NBLK*DD*FFD];
__device__ __half g_w2t[NBLK*FFD*DD];

// ---------------------------------------------------------------------------
// helpers
// ---------------------------------------------------------------------------
__device__ __forceinline__ void mma_f16(float c[4],
                                        uint32_t a0, uint32_t a1,
                                        uint32_t a2, uint32_t a3,
                                        uint32_t b0, uint32_t b1)
{
    asm volatile(
        "mma.sync.aligned.m16n8k16.row.col.f32.f16.f16.f32 "
        "{%0,%1,%2,%3}, {%4,%5,%6,%7}, {%8,%9}, {%0,%1,%2,%3};"
        : "+f"(c[0]), "+f"(c[1]), "+f"(c[2]), "+f"(c[3])
        : "r"(a0), "r"(a1), "r"(a2), "r"(a3), "r"(b0), "r"(b1));
}
__device__ __forceinline__ void cp_async16(uint32_t smem_addr, const void* gptr) {
    asm volatile("cp.async.cg.shared.global [%0], [%1], 16;"
                 :: "r"(smem_addr), "l"(gptr));
}
__device__ __forceinline__ void cp_commit() {
    asm volatile("cp.async.commit_group;");
}
template<int N>
__device__ __forceinline__ void cp_wait() {
    asm volatile("cp.async.wait_group %0;" :: "n"(N));
}
__device__ __forceinline__ uint32_t h2u(__half2 h) {
    return *(uint32_t*)&h;
}

// ---------------------------------------------------------------------------
// One-shot weight transpose + fp16 convert for ALL weights.
// W[K][N] fp32 -> Wt[N][K] fp16.  z in [0,10): (matrix, block) pairs.
// ---------------------------------------------------------------------------
__global__ void wtrans_all_kernel(
    const float* __restrict__ Wk, const float* __restrict__ Wv,
    const float* __restrict__ Wo, const float* __restrict__ W1,
    const float* __restrict__ W2,
    __half* __restrict__ twk, __half* __restrict__ twv,
    __half* __restrict__ two, __half* __restrict__ tw1,
    __half* __restrict__ tw2)
{
    const int z   = blockIdx.z;
    const int blk = z & 1;
    const float* W; __half* T; int K, N;
    switch (z >> 1) {
        case 0: W = Wk + (size_t)blk * DD * DD;  T = twk + (size_t)blk * DD * DD;  K = DD;  N = DD;  break;
        case 1: W = Wv + (size_t)blk * DD * DD;  T = twv + (size_t)blk * DD * DD;  K = DD;  N = DD;  break;
        case 2: W = Wo + (size_t)blk * DD * DD;  T = two + (size_t)blk * DD * DD;  K = DD;  N = DD;  break;
        case 3: W = W1 + (size_t)blk * DD * FFD; T = tw1 + (size_t)blk * DD * FFD; K = DD;  N = FFD; break;
        default:W = W2 + (size_t)blk * FFD * DD; T = tw2 + (size_t)blk * FFD * DD; K = FFD; N = DD;  break;
    }
    const int n0 = blockIdx.x * 32;
    const int k0 = blockIdx.y * 32;
    if (n0 >= N || k0 >= K) return;

    __shared__ float t[32][33];
    const int tx = threadIdx.x, ty = threadIdx.y;
    for (int j = ty; j < 32; j += 8)
        t[j][tx] = W[(size_t)(k0 + j) * N + n0 + tx];
    __syncthreads();
    for (int j = ty; j < 32; j += 8)
        T[(size_t)(n0 + j) * K + k0 + tx] = __float2half_rn(t[tx][j]);
}

// ---------------------------------------------------------------------------
// x = qe+pe (fp32 residual) + fp16 copies xh, yh of both streams
// ---------------------------------------------------------------------------
__global__ void add_pe_kernel(const float4* __restrict__ qe,
                              const float4* __restrict__ qa,
                              const float4* __restrict__ pe,
                              float4* __restrict__ x,
                              __half* __restrict__ xh, __half* __restrict__ yh)
{
    int i = blockIdx.x * blockDim.x + threadIdx.x;
    const int n4 = BSD / 4;
    if (i >= n4) return;
    int pi = i & (SS * DD / 4 - 1);
    float4 p = pe[pi];
    float4 a = qe[i];
    a.x += p.x; a.y += p.y; a.z += p.z; a.w += p.w;
    x[i] = a;
    ((__half2*)(xh + 4 * (size_t)i))[0] = __floats2half2_rn(a.x, a.y);
    ((__half2*)(xh + 4 * (size_t)i))[1] = __floats2half2_rn(a.z, a.w);
    float4 b = qa[i];
    b.x += p.x; b.y += p.y; b.z += p.z; b.w += p.w;
    ((__half2*)(yh + 4 * (size_t)i))[0] = __floats2half2_rn(b.x, b.y);
    ((__half2*)(yh + 4 * (size_t)i))[1] = __floats2half2_rn(b.z, b.w);
}

// ---------------------------------------------------------------------------
// FP16 tensor-core GEMM (R11 config): C[M,N] = A[M,K] @ Wt[N,K]^T + bias[N]
// 256 threads (2x4 warps, 64x32 warp tiles), BK=32, 3-stage cp.async.
// MODE 0: fp32 out. MODE 1: ReLU + fp16 out. MODE 2: fp16 out.
// ---------------------------------------------------------------------------
#define HST 40
#define HTILE (128 * HST)
#define STGH (2 * HTILE)
#define NSTG 3
#define GEMM_SMEM (NSTG * STGH * sizeof(__half))   // 61440 B

template<int MODE>
__global__ void __launch_bounds__(256, 2) f16_gemm(
    const __half* __restrict__ A0, const __half* __restrict__ W0,
    const float* __restrict__ b0p, void* __restrict__ C0,
    const __half* __restrict__ A1, const __half* __restrict__ W1p,
    const float* __restrict__ b1p, void* __restrict__ C1,
    int M, int N, int K)
{
    extern __shared__ __half smh[];

    const __half* A    = blockIdx.z ? A1  : A0;
    const __half* W    = blockIdx.z ? W1p : W0;
    const float*  bias = blockIdx.z ? b1p : b0p;
    void*         C    = blockIdx.z ? C1  : C0;

    const int tid  = threadIdx.x;
    const int lane = tid & 31;
    const int wid  = tid >> 5;
    const int wm   = wid & 1;
    const int wn   = wid >> 1;
    const int grp  = lane >> 2;
    const int tig  = lane & 3;
    const int m0   = blockIdx.y * 128;
    const int n0   = blockIdx.x * 128;

    const uint32_t sS = (uint32_t)__cvta_generic_to_shared(smh);

    const int l_row = tid >> 1;
    const int l_h0  = (tid & 1) * 16;

    float acc[4][4][4];
#pragma unroll
    for (int i = 0; i < 4; i++)
#pragma unroll
        for (int j = 0; j < 4; j++)
#pragma unroll
            for (int r = 0; r < 4; r++) acc[i][j][r] = 0.f;

    const int nk = K >> 5;

    auto load_stage = [&](int stg, int k0) {
        const uint32_t sb = sS + (uint32_t)(stg * STGH * 2);
        {
            const __half* ga = A + (size_t)(m0 + l_row) * K + k0 + l_h0;
            uint32_t da = sb + (uint32_t)((l_row * HST + l_h0) * 2);
            cp_async16(da,      ga);
            cp_async16(da + 16, ga + 8);
        }
        {
            const __half* gb = W + (size_t)(n0 + l_row) * K + k0 + l_h0;
            uint32_t db = sb + (uint32_t)((HTILE + l_row * HST + l_h0) * 2);
            cp_async16(db,      gb);
            cp_async16(db + 16, gb + 8);
        }
    };

    load_stage(0, 0);
    cp_commit();
    load_stage(1, 32);
    cp_commit();

    for (int kt = 0; kt < nk; kt++) {
        if (kt + NSTG - 1 < nk) {
            int s = kt + NSTG - 1;
            load_stage(s % NSTG, s * 32);
        }
        cp_commit();
        cp_wait<NSTG - 1>();
        __syncthreads();

        const __half* pA = smh + (kt % NSTG) * STGH;
        const __half* pB = pA + HTILE;

#pragma unroll
        for (int kk = 0; kk < 32; kk += 16) {
            uint32_t af[4][4];
            uint32_t bf[4][2];
#pragma unroll
            for (int mt = 0; mt < 4; mt++) {
                int mr = wm * 64 + mt * 16 + grp;
                af[mt][0] = *(const uint32_t*)(pA + (mr    ) * HST + kk + 2 * tig    );
                af[mt][1] = *(const uint32_t*)(pA + (mr + 8) * HST + kk + 2 * tig    );
                af[mt][2] = *(const uint32_t*)(pA + (mr    ) * HST + kk + 2 * tig + 8);
                af[mt][3] = *(const uint32_t*)(pA + (mr + 8) * HST + kk + 2 * tig + 8);
            }
#pragma unroll
            for (int nt = 0; nt < 4; nt++) {
                int nc = wn * 32 + nt * 8 + grp;
                bf[nt][0] = *(const uint32_t*)(pB + nc * HST + kk + 2 * tig    );
                bf[nt][1] = *(const uint32_t*)(pB + nc * HST + kk + 2 * tig + 8);
            }
#pragma unroll
            for (int mt = 0; mt < 4; mt++)
#pragma unroll
                for (int nt = 0; nt < 4; nt++)
                    mma_f16(acc[mt][nt],
                            af[mt][0], af[mt][1], af[mt][2], af[mt][3],
                            bf[nt][0], bf[nt][1]);
        }
        __syncthreads();
    }

#pragma unroll
    for (int mt = 0; mt < 4; mt++) {
#pragma unroll
        for (int nt = 0; nt < 4; nt++) {
            int row = m0 + wm * 64 + mt * 16 + grp;
            int col = n0 + wn * 32 + nt * 8 + tig * 2;
            float bb0 = bias[col], bb1 = bias[col + 1];
            float v0 = acc[mt][nt][0] + bb0;
            float v1 = acc[mt][nt][1] + bb1;
            float v2 = acc[mt][nt][2] + bb0;
            float v3 = acc[mt][nt][3] + bb1;
            if (MODE == 0) {
                float* Cf = (float*)C;
                *(float2*)(Cf + (size_t)row * N + col)       = make_float2(v0, v1);
                *(float2*)(Cf + (size_t)(row + 8) * N + col) = make_float2(v2, v3);
            } else {
                if (MODE == 1) {
                    v0 = fmaxf(v0, 0.f); v1 = fmaxf(v1, 0.f);
                    v2 = fmaxf(v2, 0.f); v3 = fmaxf(v3, 0.f);
                }
                __half* Ch = (__half*)C;
                *(__half2*)(Ch + (size_t)row * N + col)       = __floats2half2_rn(v0, v1);
                *(__half2*)(Ch + (size_t)(row + 8) * N + col) = __floats2half2_rn(v2, v3);
            }
        }
    }
}

// ---------------------------------------------------------------------------
// FP16 flash attention (64-row q-tiles, 128 threads).
// V stored TRANSPOSED in smem: Vt[dk][key] -> P*V B-frag is two aligned
// 32-bit loads (was 4x u16 + 2 packs).
// ---------------------------------------------------------------------------
#define APADH 72
#define ATTN_SMEM (3 * 64 * APADH * sizeof(__half))

__global__ void __launch_bounds__(128, 4) attn_f16_kernel(
    const __half* __restrict__ Q, const __half* __restrict__ V,
    const float* __restrict__ FR, __half* __restrict__ AH)
{
    extern __shared__ __half smh[];
    __half* Qs = smh;                    // [64][APADH]  (row=q, col=dk)
    __half* Ks = smh + 64 * APADH;       // [64][APADH]  (row=key, col=dk)
    __half* Vt = smh + 2 * 64 * APADH;   // [64][APADH]  (row=dk, col=key)

    const int qt   = gridDim.x - 1 - blockIdx.x;   // heavy-first
    const int bh   = blockIdx.y;
    const int b    = bh >> 3;
    const int h    = bh & 7;
    const int tid  = threadIdx.x;
    const int lane = tid & 31;
    const int w    = tid >> 5;
    const int grp  = lane >> 2;
    const int tig  = lane & 3;
    const int q0   = qt * 64;
    const size_t base = (size_t)b * SS * DD + (size_t)h * DKK;

#pragma unroll
    for (int j = 0; j < 4; j++) {
        int idx = j * 128 + tid;
        int r   = idx >> 3;
        int c8  = (idx & 7) * 8;
        *(float4*)(Qs + r * APADH + c8) =
            *(const float4*)(Q + base + (size_t)(q0 + r) * DD + c8);
    }

    const int rg0 = q0 + w * 16 + grp;
    const float frs0 = FR[b * SS + rg0]     * 0.125f;
    const float frs1 = FR[b * SS + rg0 + 8] * 0.125f;

    float m0 = -3.0e38f, m1 = -3.0e38f, l0 = 0.f, l1 = 0.f;
    float o[8][4];
#pragma unroll
    for (int nt = 0; nt < 8; nt++)
#pragma unroll
        for (int r = 0; r < 4; r++) o[nt][r] = 0.f;

    for (int kt = 0; kt <= qt; kt++) {
        __syncthreads();
#pragma unroll
        for (int j = 0; j < 4; j++) {
            int idx = j * 128 + tid;
            int r   = idx >> 3;              // key row
            int c8  = (idx & 7) * 8;         // dk base
            *(float4*)(Ks + r * APADH + c8) =
                *(const float4*)(Q + base + (size_t)(kt * 64 + r) * DD + c8);
            // V transposed store: Vt[dk][key]
            float4 vv = *(const float4*)(V + base + (size_t)(kt * 64 + r) * DD + c8);
            __half hv[8];
            *(float4*)hv = vv;
#pragma unroll
            for (int i = 0; i < 8; i++)
                Vt[(c8 + i) * APADH + r] = hv[i];
        }
        __syncthreads();

        // --- S = Q K^T (this warp's 16 rows x 64 keys), fp16 k16 ---
        float sc[8][4];
#pragma unroll
        for (int nt = 0; nt < 8; nt++)
#pragma unroll
            for (int r = 0; r < 4; r++) sc[nt][r] = 0.f;

        const int mr = w * 16 + grp;
#pragma unroll
        for (int kc = 0; kc < 4; kc++) {
            const int k0 = kc * 16;
            uint32_t a0 = *(const uint32_t*)(Qs + (mr    ) * APADH + k0 + 2 * tig    );
            uint32_t a1 = *(const uint32_t*)(Qs + (mr + 8) * APADH + k0 + 2 * tig    );
            uint32_t a2 = *(const uint32_t*)(Qs + (mr    ) * APADH + k0 + 2 * tig + 8);
            uint32_t a3 = *(const uint32_t*)(Qs + (mr + 8) * APADH + k0 + 2 * tig + 8);
#pragma unroll
            for (int nt = 0; nt < 8; nt++) {
                int nc = nt * 8 + grp;
                uint32_t b0 = *(const uint32_t*)(Ks + nc * APADH + k0 + 2 * tig    );
                uint32_t b1 = *(const uint32_t*)(Ks + nc * APADH + k0 + 2 * tig + 8);
                mma_f16(sc[nt], a0, a1, a2, a3, b0, b1);
            }
        }

        // --- scale + mask + online softmax ---
        const bool diag = (kt == qt);
        float mx0 = -3.0e38f, mx1 = -3.0e38f;
#pragma unroll
        for (int nt = 0; nt < 8; nt++) {
            int cg = kt * 64 + nt * 8 + 2 * tig;
            float s0 = sc[nt][0] * frs0;
            float s1 = sc[nt][1] * frs0;
            float s2 = sc[nt][2] * frs1;
            float s3 = sc[nt][3] * frs1;
            if (diag) {
                if (cg     >= rg0)     s0 = -1e30f;
                if (cg + 1 >= rg0)     s1 = -1e30f;
                if (cg     >= rg0 + 8) s2 = -1e30f;
                if (cg + 1 >= rg0 + 8) s3 = -1e30f;
            }
            sc[nt][0] = s0; sc[nt][1] = s1; sc[nt][2] = s2; sc[nt][3] = s3;
            mx0 = fmaxf(mx0, fmaxf(s0, s1));
            mx1 = fmaxf(mx1, fmaxf(s2, s3));
        }
        mx0 = fmaxf(mx0, __shfl_xor_sync(0xffffffffu, mx0, 1));
        mx0 = fmaxf(mx0, __shfl_xor_sync(0xffffffffu, mx0, 2));
        mx1 = fmaxf(mx1, __shfl_xor_sync(0xffffffffu, mx1, 1));
        mx1 = fmaxf(mx1, __shfl_xor_sync(0xffffffffu, mx1, 2));

        float mn0 = fmaxf(m0, mx0);
        float mn1 = fmaxf(m1, mx1);
        float al0 = __expf(m0 - mn0);
        float al1 = __expf(m1 - mn1);
        m0 = mn0; m1 = mn1;

        float su0 = 0.f, su1 = 0.f;
        uint32_t pu[8][2];
#pragma unroll
        for (int nt = 0; nt < 8; nt++) {
            float p0 = __expf(sc[nt][0] - mn0);
            float p1 = __expf(sc[nt][1] - mn0);
            float p2 = __expf(sc[nt][2] - mn1);
            float p3 = __expf(sc[nt][3] - mn1);
            su0 += p0 + p1;
            su1 += p2 + p3;
            pu[nt][0] = h2u(__floats2half2_rn(p0, p1));
            pu[nt][1] = h2u(__floats2half2_rn(p2, p3));
        }
        su0 += __shfl_xor_sync(0xffffffffu, su0, 1);
        su0 += __shfl_xor_sync(0xffffffffu, su0, 2);
        su1 += __shfl_xor_sync(0xffffffffu, su1, 1);
        su1 += __shfl_xor_sync(0xffffffffu, su1, 2);
        l0 = l0 * al0 + su0;
        l1 = l1 * al1 + su1;
#pragma unroll
        for (int nt = 0; nt < 8; nt++) {
            o[nt][0] *= al0; o[nt][1] *= al0;
            o[nt][2] *= al1; o[nt][3] *= al1;
        }

        // --- O += P V : A-frag = packed C-frag, B-frag = 32-bit Vt loads ---
#pragma unroll
        for (int j = 0; j < 4; j++) {
            const int k0 = j * 16;
            uint32_t a0 = pu[2 * j    ][0];
            uint32_t a1 = pu[2 * j    ][1];
            uint32_t a2 = pu[2 * j + 1][0];
            uint32_t a3 = pu[2 * j + 1][1];
#pragma unroll
            for (int nt = 0; nt < 8; nt++) {
                int n = nt * 8 + grp;
                uint32_t b0 = *(const uint32_t*)(Vt + n * APADH + k0 + 2 * tig    );
                uint32_t b1 = *(const uint32_t*)(Vt + n * APADH + k0 + 2 * tig + 8);
                mma_f16(o[nt], a0, a1, a2, a3, b0, b1);
            }
        }
    }

    float inv0 = (rg0 == 0) ? 0.f : (1.0f / l0);
    float inv1 = 1.0f / l1;
#pragma unroll
    for (int nt = 0; nt < 8; nt++) {
        int col = nt * 8 + tig * 2;
        *(__half2*)(AH + base + (size_t)(rg0    ) * DD + col) =
            __floats2half2_rn(o[nt][0] * inv0, o[nt][1] * inv0);
        *(__half2*)(AH + base + (size_t)(rg0 + 8) * DD + col) =
            __floats2half2_rn(o[nt][2] * inv1, o[nt][3] * inv1);
    }
}

// ---------------------------------------------------------------------------
// out = LayerNorm(x + r)*g + be; optional fp16 copy outh
// ---------------------------------------------------------------------------
__global__ void __launch_bounds__(128) ln_res_kernel(
    const float* __restrict__ x, const float* __restrict__ r,
    const float* __restrict__ g, const float* __restrict__ be,
    float* __restrict__ out, __half* __restrict__ outh)
{
    int row = blockIdx.x;
    int tid = threadIdx.x;
    const float4* xp = (const float4*)(x + (size_t)row * DD);
    const float4* rp = (const float4*)(r + (size_t)row * DD);
    float4 v = xp[tid], w = rp[tid];
    v.x += w.x; v.y += w.y; v.z += w.z; v.w += w.w;
    float s  = v.x + v.y + v.z + v.w;
    float ss = v.x * v.x + v.y * v.y + v.z * v.z + v.w * v.w;
#pragma unroll
    for (int ofs = 16; ofs > 0; ofs >>= 1) {
        s  += __shfl_xor_sync(0xffffffffu, s,  ofs);
        ss += __shfl_xor_sync(0xffffffffu, ss, ofs);
    }
    __shared__ float sb[4], ssb[4];
    int wid = tid >> 5;
    if ((tid & 31) == 0) { sb[wid] = s; ssb[wid] = ss; }
    __syncthreads();
    s  = sb[0]  + sb[1]  + sb[2]  + sb[3];
    ss = ssb[0] + ssb[1] + ssb[2] + ssb[3];
    float mean = s * (1.0f / DD);
    float var  = ss * (1.0f / DD) - mean * mean;
    float rs   = rsqrtf(var + 1e-5f);
    float4 gv = ((const float4*)g)[tid];
    float4 bv = ((const float4*)be)[tid];
    float4 o4;
    o4.x = (v.x - mean) * rs * gv.x + bv.x;
    o4.y = (v.y - mean) * rs * gv.y + bv.y;
    o4.z = (v.z - mean) * rs * gv.z + bv.z;
    o4.w = (v.w - mean) * rs * gv.w + bv.w;
    ((float4*)(out + (size_t)row * DD))[tid] = o4;
    if (outh) {
        size_t e = (size_t)row * DD + tid * 4;
        ((__half2*)(outh + e))[0] = __floats2half2_rn(o4.x, o4.y);
        ((__half2*)(outh + e))[1] = __floats2half2_rn(o4.z, o4.w);
    }
}

// ---------------------------------------------------------------------------
extern "C" void kernel_launch(void* const* d_in, const int* in_sizes, int n_in,
                              void* d_out, int out_size)
{
    const float* qe  = (const float*)d_in[0];
    const float* qa  = (const float*)d_in[1];
    const float* fr  = (const float*)d_in[2];
    const float* pe  = (const float*)d_in[3];
    const float* Wk  = (const float*)d_in[4];
    const float* bk  = (const float*)d_in[5];
    const float* Wv  = (const float*)d_in[6];
    const float* bv  = (const float*)d_in[7];
    const float* Wo  = (const float*)d_in[8];
    const float* bo  = (const float*)d_in[9];
    const float* g1  = (const float*)d_in[10];
    const float* be1 = (const float*)d_in[11];
    const float* W1  = (const float*)d_in[12];
    const float* bf1 = (const float*)d_in[13];
    const float* W2  = (const float*)d_in[14];
    const float* bf2 = (const float*)d_in[15];
    const float* g2  = (const float*)d_in[16];
    const float* be2 = (const float*)d_in[17];
    float* out = (float*)d_out;

    float  *px, *pt;
    __half *pqh, *pvh, *pxh, *pyh, *pah, *pfh, *pwkt, *pwvt, *pwot, *pw1t, *pw2t;
    cudaGetSymbolAddress((void**)&px,   g_x);
    cudaGetSymbolAddress((void**)&pt,   g_t);
    cudaGetSymbolAddress((void**)&pqh,  g_qh);
    cudaGetSymbolAddress((void**)&pvh,  g_vh);
    cudaGetSymbolAddress((void**)&pxh,  g_xh);
    cudaGetSymbolAddress((void**)&pyh,  g_yh);
    cudaGetSymbolAddress((void**)&pah,  g_ah);
    cudaGetSymbolAddress((void**)&pfh,  g_fh);
    cudaGetSymbolAddress((void**)&pwkt, g_wkt);
    cudaGetSymbolAddress((void**)&pwvt, g_wvt);
    cudaGetSymbolAddress((void**)&pwot, g_wot);
    cudaGetSymbolAddress((void**)&pw1t, g_w1t);
    cudaGetSymbolAddress((void**)&pw2t, g_w2t);

    cudaFuncSetAttribute(attn_f16_kernel,
                         cudaFuncAttributeMaxDynamicSharedMemorySize, (int)ATTN_SMEM);
    cudaFuncSetAttribute(f16_gemm<0>,
                         cudaFuncAttributeMaxDynamicSharedMemorySize, (int)GEMM_SMEM);
    cudaFuncSetAttribute(f16_gemm<1>,
                         cudaFuncAttributeMaxDynamicSharedMemorySize, (int)GEMM_SMEM);
    cudaFuncSetAttribute(f16_gemm<2>,
                         cudaFuncAttributeMaxDynamicSharedMemorySize, (int)GEMM_SMEM);

    wtrans_all_kernel<<<dim3(64, 64, 10), dim3(32, 8)>>>(
        Wk, Wv, Wo, W1, W2, pwkt, pwvt, pwot, pw1t, pw2t);

    add_pe_kernel<<<(BSD / 4 + 255) / 256, 256>>>(
        (const float4*)qe, (const float4*)qa, (const float4*)pe,
        (float4*)px, pxh, pyh);

    dim3 g512 (DD / 128, MTOK / 128, 1);   // (4, 128)
    dim3 g512z(DD / 128, MTOK / 128, 2);   // merged q & v
    dim3 gff  (FFD / 128, MTOK / 128, 1);  // (16, 128)
    dim3 gattn(SS / 64, BB * HH);          // (8, 256)

    for (int i = 0; i < NBLK; i++) {
        const __half* wkt = pwkt + (size_t)i * DD * DD;
        const __half* wvt = pwvt + (size_t)i * DD * DD;
        const __half* wot = pwot + (size_t)i * DD * DD;
        const __half* w1t = pw1t + (size_t)i * DD * FFD;
        const __half* w2t = pw2t + (size_t)i * FFD * DD;

        // merged: z=0 -> q = x@Wk + bk (fp16) ; z=1 -> v = y@Wv + bv (fp16)
        f16_gemm<2><<<g512z, 256, GEMM_SMEM>>>(
            pxh, wkt, bk + i * DD, pqh,
            pyh, wvt, bv + i * DD, pvh, MTOK, DD, DD);
        // attention (fp16 in/out)
        attn_f16_kernel<<<gattn, 128, ATTN_SMEM>>>(pqh, pvh, fr, pah);
        // proj = ah @ Wo + bo -> pt (fp32)
        f16_gemm<0><<<g512, 256, GEMM_SMEM>>>(
            pah, wot, bo + i * DD, pt,
            pah, wot, bo + i * DD, pt, MTOK, DD, DD);
        // x = LN(x + proj); xh = fp16(x)
        ln_res_kernel<<<MTOK, 128>>>(px, pt, g1 + i * DD, be1 + i * DD, px, pxh);
        // hidden = relu(x @ W1 + bf1) -> fp16 fh
        f16_gemm<1><<<gff, 256, GEMM_SMEM>>>(
            pxh, w1t, bf1 + i * FFD, pfh,
            pxh, w1t, bf1 + i * FFD, pfh, MTOK, FFD, DD);
        // ffn = fh @ W2 + bf2 -> pt (fp32)
        f16_gemm<0><<<g512, 256, GEMM_SMEM>>>(
            pfh, w2t, bf2 + i * DD, pt,
            pfh, w2t, bf2 + i * DD, pt, MTOK, DD, FFD);
        // x = LN(x + ffn)
        float*  dst = (i == NBLK - 1) ? out : px;
        __half* dh  = (i == NBLK - 1) ? nullptr : pxh;
        ln_res_kernel<<<MTOK, 128>>>(px, pt, g2 + i * DD, be2 + i * DD, dst, dh);
    }
}

// round 15
// speedup vs baseline: 1.0526x; 1.0526x over previous
#include <cuda_runtime.h>
#include <cuda_fp16.h>
#include <math.h>
#include <stdint.h>

// Problem constants
#define BB   32
#define SS   512
#define DD   512
#define HH   8
#define DKK  64
#define FFD  2048
#define NBLK 2
#define MTOK (BB*SS)            // 16384 token rows
#define BSD  (BB*SS*DD)         // 8388608
#define BSF  (BB*SS*FFD)        // 33554432

// Scratch (static device globals — no allocation allowed)
__device__ float  g_x[BSD];          // residual stream (fp32)
__device__ float  g_t[BSD];          // fp32 temp (proj / ffn out)
__device__ __half g_qh[BSD];         // q (fp16, attn input)
__device__ __half g_vh[BSD];         // v (fp16, attn input)
__device__ __half g_xh[BSD];         // fp16 activations
__device__ __half g_yh[BSD];
__device__ __half g_ah[BSD];         // attn output (fp16)
__device__ __half g_fh[BSF];         // ffn hidden (fp16)
__device__ __half g_wkt[NBLK*DD*DD]; // transposed fp16 weights [N][K]
__device__ __half g_wvt[NBLK*DD*DD];
__device__ __half g_wot[NBLK*DD*DD];
__device__ __half g_w1t[NBLK*DD*FFD];
__device__ __half g_w2t[NBLK*FFD*DD];

// ---------------------------------------------------------------------------
// helpers
// ---------------------------------------------------------------------------
__device__ __forceinline__ void mma_f16(float c[4],
                                        uint32_t a0, uint32_t a1,
                                        uint32_t a2, uint32_t a3,
                                        uint32_t b0, uint32_t b1)
{
    asm volatile(
        "mma.sync.aligned.m16n8k16.row.col.f32.f16.f16.f32 "
        "{%0,%1,%2,%3}, {%4,%5,%6,%7}, {%8,%9}, {%0,%1,%2,%3};"
        : "+f"(c[0]), "+f"(c[1]), "+f"(c[2]), "+f"(c[3])
        : "r"(a0), "r"(a1), "r"(a2), "r"(a3), "r"(b0), "r"(b1));
}
__device__ __forceinline__ void cp_async16(uint32_t smem_addr, const void* gptr) {
    asm volatile("cp.async.cg.shared.global [%0], [%1], 16;"
                 :: "r"(smem_addr), "l"(gptr));
}
__device__ __forceinline__ void cp_commit() {
    asm volatile("cp.async.commit_group;");
}
template<int N>
__device__ __forceinline__ void cp_wait() {
    asm volatile("cp.async.wait_group %0;" :: "n"(N));
}
__device__ __forceinline__ uint32_t pack_h2(__half lo, __half hi) {
    __half2 h; h.x = lo; h.y = hi;
    return *(uint32_t*)&h;
}
__device__ __forceinline__ uint32_t h2u(__half2 h) {
    return *(uint32_t*)&h;
}

// ---------------------------------------------------------------------------
// One-shot weight transpose + fp16 convert for ALL weights.
// W[K][N] fp32 -> Wt[N][K] fp16.  z in [0,10): (matrix, block) pairs.
// ---------------------------------------------------------------------------
__global__ void wtrans_all_kernel(
    const float* __restrict__ Wk, const float* __restrict__ Wv,
    const float* __restrict__ Wo, const float* __restrict__ W1,
    const float* __restrict__ W2,
    __half* __restrict__ twk, __half* __restrict__ twv,
    __half* __restrict__ two, __half* __restrict__ tw1,
    __half* __restrict__ tw2)
{
    const int z   = blockIdx.z;
    const int blk = z & 1;
    const float* W; __half* T; int K, N;
    switch (z >> 1) {
        case 0: W = Wk + (size_t)blk * DD * DD;  T = twk + (size_t)blk * DD * DD;  K = DD;  N = DD;  break;
        case 1: W = Wv + (size_t)blk * DD * DD;  T = twv + (size_t)blk * DD * DD;  K = DD;  N = DD;  break;
        case 2: W = Wo + (size_t)blk * DD * DD;  T = two + (size_t)blk * DD * DD;  K = DD;  N = DD;  break;
        case 3: W = W1 + (size_t)blk * DD * FFD; T = tw1 + (size_t)blk * DD * FFD; K = DD;  N = FFD; break;
        default:W = W2 + (size_t)blk * FFD * DD; T = tw2 + (size_t)blk * FFD * DD; K = FFD; N = DD;  break;
    }
    const int n0 = blockIdx.x * 32;
    const int k0 = blockIdx.y * 32;
    if (n0 >= N || k0 >= K) return;

    __shared__ float t[32][33];
    const int tx = threadIdx.x, ty = threadIdx.y;
    for (int j = ty; j < 32; j += 8)
        t[j][tx] = W[(size_t)(k0 + j) * N + n0 + tx];
    __syncthreads();
    for (int j = ty; j < 32; j += 8)
        T[(size_t)(n0 + j) * K + k0 + tx] = __float2half_rn(t[tx][j]);
}

// ---------------------------------------------------------------------------
// x = qe+pe (fp32 residual) + fp16 copies xh, yh of both streams
// ---------------------------------------------------------------------------
__global__ void add_pe_kernel(const float4* __restrict__ qe,
                              const float4* __restrict__ qa,
                              const float4* __restrict__ pe,
                              float4* __restrict__ x,
                              __half* __restrict__ xh, __half* __restrict__ yh)
{
    int i = blockIdx.x * blockDim.x + threadIdx.x;
    const int n4 = BSD / 4;
    if (i >= n4) return;
    int pi = i & (SS * DD / 4 - 1);
    float4 p = pe[pi];
    float4 a = qe[i];
    a.x += p.x; a.y += p.y; a.z += p.z; a.w += p.w;
    x[i] = a;
    ((__half2*)(xh + 4 * (size_t)i))[0] = __floats2half2_rn(a.x, a.y);
    ((__half2*)(xh + 4 * (size_t)i))[1] = __floats2half2_rn(a.z, a.w);
    float4 b = qa[i];
    b.x += p.x; b.y += p.y; b.z += p.z; b.w += p.w;
    ((__half2*)(yh + 4 * (size_t)i))[0] = __floats2half2_rn(b.x, b.y);
    ((__half2*)(yh + 4 * (size_t)i))[1] = __floats2half2_rn(b.z, b.w);
}

// ---------------------------------------------------------------------------
// FP16 tensor-core GEMM (R11 config): C[M,N] = A[M,K] @ Wt[N,K]^T + bias[N]
// 256 threads (2x4 warps, 64x32 warp tiles), BK=32, 3-stage cp.async.
// MODE 0: fp32 out. MODE 1: ReLU + fp16 out. MODE 2: fp16 out.
// ---------------------------------------------------------------------------
#define HST 40
#define HTILE (128 * HST)
#define STGH (2 * HTILE)
#define NSTG 3
#define GEMM_SMEM (NSTG * STGH * sizeof(__half))   // 61440 B

template<int MODE>
__global__ void __launch_bounds__(256, 2) f16_gemm(
    const __half* __restrict__ A0, const __half* __restrict__ W0,
    const float* __restrict__ b0p, void* __restrict__ C0,
    const __half* __restrict__ A1, const __half* __restrict__ W1p,
    const float* __restrict__ b1p, void* __restrict__ C1,
    int M, int N, int K)
{
    extern __shared__ __half smh[];

    const __half* A    = blockIdx.z ? A1  : A0;
    const __half* W    = blockIdx.z ? W1p : W0;
    const float*  bias = blockIdx.z ? b1p : b0p;
    void*         C    = blockIdx.z ? C1  : C0;

    const int tid  = threadIdx.x;
    const int lane = tid & 31;
    const int wid  = tid >> 5;
    const int wm   = wid & 1;
    const int wn   = wid >> 1;
    const int grp  = lane >> 2;
    const int tig  = lane & 3;
    const int m0   = blockIdx.y * 128;
    const int n0   = blockIdx.x * 128;

    const uint32_t sS = (uint32_t)__cvta_generic_to_shared(smh);

    const int l_row = tid >> 1;
    const int l_h0  = (tid & 1) * 16;

    float acc[4][4][4];
#pragma unroll
    for (int i = 0; i < 4; i++)
#pragma unroll
        for (int j = 0; j < 4; j++)
#pragma unroll
            for (int r = 0; r < 4; r++) acc[i][j][r] = 0.f;

    const int nk = K >> 5;

    auto load_stage = [&](int stg, int k0) {
        const uint32_t sb = sS + (uint32_t)(stg * STGH * 2);
        {
            const __half* ga = A + (size_t)(m0 + l_row) * K + k0 + l_h0;
            uint32_t da = sb + (uint32_t)((l_row * HST + l_h0) * 2);
            cp_async16(da,      ga);
            cp_async16(da + 16, ga + 8);
        }
        {
            const __half* gb = W + (size_t)(n0 + l_row) * K + k0 + l_h0;
            uint32_t db = sb + (uint32_t)((HTILE + l_row * HST + l_h0) * 2);
            cp_async16(db,      gb);
            cp_async16(db + 16, gb + 8);
        }
    };

    load_stage(0, 0);
    cp_commit();
    load_stage(1, 32);
    cp_commit();

    for (int kt = 0; kt < nk; kt++) {
        if (kt + NSTG - 1 < nk) {
            int s = kt + NSTG - 1;
            load_stage(s % NSTG, s * 32);
        }
        cp_commit();
        cp_wait<NSTG - 1>();
        __syncthreads();

        const __half* pA = smh + (kt % NSTG) * STGH;
        const __half* pB = pA + HTILE;

#pragma unroll
        for (int kk = 0; kk < 32; kk += 16) {
            uint32_t af[4][4];
            uint32_t bf[4][2];
#pragma unroll
            for (int mt = 0; mt < 4; mt++) {
                int mr = wm * 64 + mt * 16 + grp;
                af[mt][0] = *(const uint32_t*)(pA + (mr    ) * HST + kk + 2 * tig    );
                af[mt][1] = *(const uint32_t*)(pA + (mr + 8) * HST + kk + 2 * tig    );
                af[mt][2] = *(const uint32_t*)(pA + (mr    ) * HST + kk + 2 * tig + 8);
                af[mt][3] = *(const uint32_t*)(pA + (mr + 8) * HST + kk + 2 * tig + 8);
            }
#pragma unroll
            for (int nt = 0; nt < 4; nt++) {
                int nc = wn * 32 + nt * 8 + grp;
                bf[nt][0] = *(const uint32_t*)(pB + nc * HST + kk + 2 * tig    );
                bf[nt][1] = *(const uint32_t*)(pB + nc * HST + kk + 2 * tig + 8);
            }
#pragma unroll
            for (int mt = 0; mt < 4; mt++)
#pragma unroll
                for (int nt = 0; nt < 4; nt++)
                    mma_f16(acc[mt][nt],
                            af[mt][0], af[mt][1], af[mt][2], af[mt][3],
                            bf[nt][0], bf[nt][1]);
        }
        __syncthreads();
    }

#pragma unroll
    for (int mt = 0; mt < 4; mt++) {
#pragma unroll
        for (int nt = 0; nt < 4; nt++) {
            int row = m0 + wm * 64 + mt * 16 + grp;
            int col = n0 + wn * 32 + nt * 8 + tig * 2;
            float bb0 = bias[col], bb1 = bias[col + 1];
            float v0 = acc[mt][nt][0] + bb0;
            float v1 = acc[mt][nt][1] + bb1;
            float v2 = acc[mt][nt][2] + bb0;
            float v3 = acc[mt][nt][3] + bb1;
            if (MODE == 0) {
                float* Cf = (float*)C;
                *(float2*)(Cf + (size_t)row * N + col)       = make_float2(v0, v1);
                *(float2*)(Cf + (size_t)(row + 8) * N + col) = make_float2(v2, v3);
            } else {
                if (MODE == 1) {
                    v0 = fmaxf(v0, 0.f); v1 = fmaxf(v1, 0.f);
                    v2 = fmaxf(v2, 0.f); v3 = fmaxf(v3, 0.f);
                }
                __half* Ch = (__half*)C;
                *(__half2*)(Ch + (size_t)row * N + col)       = __floats2half2_rn(v0, v1);
                *(__half2*)(Ch + (size_t)(row + 8) * N + col) = __floats2half2_rn(v2, v3);
            }
        }
    }
}

// ---------------------------------------------------------------------------
// FP16 flash attention (R11 core) + double-buffered cp.async K/V tiles.
// Smem: Qs[64][72] + 2x Ks[64][72] + 2x Vs[64][72] halves (46080 B).
// ---------------------------------------------------------------------------
#define APADH 72
#define ATILE (64 * APADH)
#define ATTN_SMEM (5 * ATILE * sizeof(__half))

__global__ void __launch_bounds__(128, 4) attn_f16_kernel(
    const __half* __restrict__ Q, const __half* __restrict__ V,
    const float* __restrict__ FR, __half* __restrict__ AH)
{
    extern __shared__ __half smh[];
    __half* Qs = smh;                        // [64][APADH]

    const int qt   = gridDim.x - 1 - blockIdx.x;   // heavy-first
    const int bh   = blockIdx.y;
    const int b    = bh >> 3;
    const int h    = bh & 7;
    const int tid  = threadIdx.x;
    const int lane = tid & 31;
    const int w    = tid >> 5;
    const int grp  = lane >> 2;
    const int tig  = lane & 3;
    const int q0   = qt * 64;
    const size_t base = (size_t)b * SS * DD + (size_t)h * DKK;

    const uint32_t sB = (uint32_t)__cvta_generic_to_shared(smh);
    // buffers: K0 at tile1, V0 at tile2, K1 at tile3, V1 at tile4
    const int l_r  = tid >> 3;            // 0..15 (row base, 4 iters of +16)
    const int l_c8 = (tid & 7) * 8;       // dk chunk

    auto load_kv = [&](int buf, int kt) {
        const uint32_t kb = sB + (uint32_t)((1 + 2 * buf) * ATILE * 2);
        const uint32_t vb = sB + (uint32_t)((2 + 2 * buf) * ATILE * 2);
#pragma unroll
        for (int j = 0; j < 4; j++) {
            int r = l_r + 16 * j;
            const __half* gk = Q + base + (size_t)(kt * 64 + r) * DD + l_c8;
            const __half* gv = V + base + (size_t)(kt * 64 + r) * DD + l_c8;
            uint32_t off = (uint32_t)((r * APADH + l_c8) * 2);
            cp_async16(kb + off, gk);
            cp_async16(vb + off, gv);
        }
    };

    // load Q tile (plain; covered by first __syncthreads)
#pragma unroll
    for (int j = 0; j < 4; j++) {
        int idx = j * 128 + tid;
        int r   = idx >> 3;
        int c8  = (idx & 7) * 8;
        *(float4*)(Qs + r * APADH + c8) =
            *(const float4*)(Q + base + (size_t)(q0 + r) * DD + c8);
    }

    const int rg0 = q0 + w * 16 + grp;
    const float frs0 = FR[b * SS + rg0]     * 0.125f;
    const float frs1 = FR[b * SS + rg0 + 8] * 0.125f;

    float m0 = -3.0e38f, m1 = -3.0e38f, l0 = 0.f, l1 = 0.f;
    float o[8][4];
#pragma unroll
    for (int nt = 0; nt < 8; nt++)
#pragma unroll
        for (int r = 0; r < 4; r++) o[nt][r] = 0.f;

    load_kv(0, 0);
    cp_commit();

    for (int kt = 0; kt <= qt; kt++) {
        if (kt + 1 <= qt) load_kv((kt + 1) & 1, kt + 1);
        cp_commit();
        cp_wait<1>();
        __syncthreads();

        const __half* Ks = smh + (1 + 2 * (kt & 1)) * ATILE;
        const __half* Vs = smh + (2 + 2 * (kt & 1)) * ATILE;

        // --- S = Q K^T (this warp's 16 rows x 64 keys), fp16 k16 ---
        float sc[8][4];
#pragma unroll
        for (int nt = 0; nt < 8; nt++)
#pragma unroll
            for (int r = 0; r < 4; r++) sc[nt][r] = 0.f;

        const int mr = w * 16 + grp;
#pragma unroll
        for (int kc = 0; kc < 4; kc++) {
            const int k0 = kc * 16;
            uint32_t a0 = *(const uint32_t*)(Qs + (mr    ) * APADH + k0 + 2 * tig    );
            uint32_t a1 = *(const uint32_t*)(Qs + (mr + 8) * APADH + k0 + 2 * tig    );
            uint32_t a2 = *(const uint32_t*)(Qs + (mr    ) * APADH + k0 + 2 * tig + 8);
            uint32_t a3 = *(const uint32_t*)(Qs + (mr + 8) * APADH + k0 + 2 * tig + 8);
#pragma unroll
            for (int nt = 0; nt < 8; nt++) {
                int nc = nt * 8 + grp;
                uint32_t b0 = *(const uint32_t*)(Ks + nc * APADH + k0 + 2 * tig    );
                uint32_t b1 = *(const uint32_t*)(Ks + nc * APADH + k0 + 2 * tig + 8);
                mma_f16(sc[nt], a0, a1, a2, a3, b0, b1);
            }
        }

        // --- scale + mask + online softmax ---
        const bool diag = (kt == qt);
        float mx0 = -3.0e38f, mx1 = -3.0e38f;
#pragma unroll
        for (int nt = 0; nt < 8; nt++) {
            int cg = kt * 64 + nt * 8 + 2 * tig;
            float s0 = sc[nt][0] * frs0;
            float s1 = sc[nt][1] * frs0;
            float s2 = sc[nt][2] * frs1;
            float s3 = sc[nt][3] * frs1;
            if (diag) {
                if (cg     >= rg0)     s0 = -1e30f;
                if (cg + 1 >= rg0)     s1 = -1e30f;
                if (cg     >= rg0 + 8) s2 = -1e30f;
                if (cg + 1 >= rg0 + 8) s3 = -1e30f;
            }
            sc[nt][0] = s0; sc[nt][1] = s1; sc[nt][2] = s2; sc[nt][3] = s3;
            mx0 = fmaxf(mx0, fmaxf(s0, s1));
            mx1 = fmaxf(mx1, fmaxf(s2, s3));
        }
        mx0 = fmaxf(mx0, __shfl_xor_sync(0xffffffffu, mx0, 1));
        mx0 = fmaxf(mx0, __shfl_xor_sync(0xffffffffu, mx0, 2));
        mx1 = fmaxf(mx1, __shfl_xor_sync(0xffffffffu, mx1, 1));
        mx1 = fmaxf(mx1, __shfl_xor_sync(0xffffffffu, mx1, 2));

        float mn0 = fmaxf(m0, mx0);
        float mn1 = fmaxf(m1, mx1);
        float al0 = __expf(m0 - mn0);
        float al1 = __expf(m1 - mn1);
        m0 = mn0; m1 = mn1;

        float su0 = 0.f, su1 = 0.f;
        uint32_t pu[8][2];
#pragma unroll
        for (int nt = 0; nt < 8; nt++) {
            float p0 = __expf(sc[nt][0] - mn0);
            float p1 = __expf(sc[nt][1] - mn0);
            float p2 = __expf(sc[nt][2] - mn1);
            float p3 = __expf(sc[nt][3] - mn1);
            su0 += p0 + p1;
            su1 += p2 + p3;
            pu[nt][0] = h2u(__floats2half2_rn(p0, p1));
            pu[nt][1] = h2u(__floats2half2_rn(p2, p3));
        }
        su0 += __shfl_xor_sync(0xffffffffu, su0, 1);
        su0 += __shfl_xor_sync(0xffffffffu, su0, 2);
        su1 += __shfl_xor_sync(0xffffffffu, su1, 1);
        su1 += __shfl_xor_sync(0xffffffffu, su1, 2);
        l0 = l0 * al0 + su0;
        l1 = l1 * al1 + su1;
#pragma unroll
        for (int nt = 0; nt < 8; nt++) {
            o[nt][0] *= al0; o[nt][1] *= al0;
            o[nt][2] *= al1; o[nt][3] *= al1;
        }

        // --- O += P V : A-frag = packed C-frag, B via 2x u16 loads ---
#pragma unroll
        for (int j = 0; j < 4; j++) {
            const int k0 = j * 16;
            uint32_t a0 = pu[2 * j    ][0];
            uint32_t a1 = pu[2 * j    ][1];
            uint32_t a2 = pu[2 * j + 1][0];
            uint32_t a3 = pu[2 * j + 1][1];
#pragma unroll
            for (int nt = 0; nt < 8; nt++) {
                int n = nt * 8 + grp;
                uint32_t b0 = pack_h2(Vs[(k0 + 2 * tig    ) * APADH + n],
                                      Vs[(k0 + 2 * tig + 1) * APADH + n]);
                uint32_t b1 = pack_h2(Vs[(k0 + 2 * tig + 8) * APADH + n],
                                      Vs[(k0 + 2 * tig + 9) * APADH + n]);
                mma_f16(o[nt], a0, a1, a2, a3, b0, b1);
            }
        }
        __syncthreads();   // compute done before buffer (kt+2)%2 refill
    }

    float inv0 = (rg0 == 0) ? 0.f : (1.0f / l0);
    float inv1 = 1.0f / l1;
#pragma unroll
    for (int nt = 0; nt < 8; nt++) {
        int col = nt * 8 + tig * 2;
        *(__half2*)(AH + base + (size_t)(rg0    ) * DD + col) =
            __floats2half2_rn(o[nt][0] * inv0, o[nt][1] * inv0);
        *(__half2*)(AH + base + (size_t)(rg0 + 8) * DD + col) =
            __floats2half2_rn(o[nt][2] * inv1, o[nt][3] * inv1);
    }
}

// ---------------------------------------------------------------------------
// out = LayerNorm(x + r)*g + be; optional fp16 copy outh
// ---------------------------------------------------------------------------
__global__ void __launch_bounds__(128) ln_res_kernel(
    const float* __restrict__ x, const float* __restrict__ r,
    const float* __restrict__ g, const float* __restrict__ be,
    float* __restrict__ out, __half* __restrict__ outh)
{
    int row = blockIdx.x;
    int tid = threadIdx.x;
    const float4* xp = (const float4*)(x + (size_t)row * DD);
    const float4* rp = (const float4*)(r + (size_t)row * DD);
    float4 v = xp[tid], w = rp[tid];
    v.x += w.x; v.y += w.y; v.z += w.z; v.w += w.w;
    float s  = v.x + v.y + v.z + v.w;
    float ss = v.x * v.x + v.y * v.y + v.z * v.z + v.w * v.w;
#pragma unroll
    for (int ofs = 16; ofs > 0; ofs >>= 1) {
        s  += __shfl_xor_sync(0xffffffffu, s,  ofs);
        ss += __shfl_xor_sync(0xffffffffu, ss, ofs);
    }
    __shared__ float sb[4], ssb[4];
    int wid = tid >> 5;
    if ((tid & 31) == 0) { sb[wid] = s; ssb[wid] = ss; }
    __syncthreads();
    s  = sb[0]  + sb[1]  + sb[2]  + sb[3];
    ss = ssb[0] + ssb[1] + ssb[2] + ssb[3];
    float mean = s * (1.0f / DD);
    float var  = ss * (1.0f / DD) - mean * mean;
    float rs   = rsqrtf(var + 1e-5f);
    float4 gv = ((const float4*)g)[tid];
    float4 bv = ((const float4*)be)[tid];
    float4 o4;
    o4.x = (v.x - mean) * rs * gv.x + bv.x;
    o4.y = (v.y - mean) * rs * gv.y + bv.y;
    o4.z = (v.z - mean) * rs * gv.z + bv.z;
    o4.w = (v.w - mean) * rs * gv.w + bv.w;
    ((float4*)(out + (size_t)row * DD))[tid] = o4;
    if (outh) {
        size_t e = (size_t)row * DD + tid * 4;
        ((__half2*)(outh + e))[0] = __floats2half2_rn(o4.x, o4.y);
        ((__half2*)(outh + e))[1] = __floats2half2_rn(o4.z, o4.w);
    }
}

// ---------------------------------------------------------------------------
extern "C" void kernel_launch(void* const* d_in, const int* in_sizes, int n_in,
                              void* d_out, int out_size)
{
    const float* qe  = (const float*)d_in[0];
    const float* qa  = (const float*)d_in[1];
    const float* fr  = (const float*)d_in[2];
    const float* pe  = (const float*)d_in[3];
    const float* Wk  = (const float*)d_in[4];
    const float* bk  = (const float*)d_in[5];
    const float* Wv  = (const float*)d_in[6];
    const float* bv  = (const float*)d_in[7];
    const float* Wo  = (const float*)d_in[8];
    const float* bo  = (const float*)d_in[9];
    const float* g1  = (const float*)d_in[10];
    const float* be1 = (const float*)d_in[11];
    const float* W1  = (const float*)d_in[12];
    const float* bf1 = (const float*)d_in[13];
    const float* W2  = (const float*)d_in[14];
    const float* bf2 = (const float*)d_in[15];
    const float* g2  = (const float*)d_in[16];
    const float* be2 = (const float*)d_in[17];
    float* out = (float*)d_out;

    float  *px, *pt;
    __half *pqh, *pvh, *pxh, *pyh, *pah, *pfh, *pwkt, *pwvt, *pwot, *pw1t, *pw2t;
    cudaGetSymbolAddress((void**)&px,   g_x);
    cudaGetSymbolAddress((void**)&pt,   g_t);
    cudaGetSymbolAddress((void**)&pqh,  g_qh);
    cudaGetSymbolAddress((void**)&pvh,  g_vh);
    cudaGetSymbolAddress((void**)&pxh,  g_xh);
    cudaGetSymbolAddress((void**)&pyh,  g_yh);
    cudaGetSymbolAddress((void**)&pah,  g_ah);
    cudaGetSymbolAddress((void**)&pfh,  g_fh);
    cudaGetSymbolAddress((void**)&pwkt, g_wkt);
    cudaGetSymbolAddress((void**)&pwvt, g_wvt);
    cudaGetSymbolAddress((void**)&pwot, g_wot);
    cudaGetSymbolAddress((void**)&pw1t, g_w1t);
    cudaGetSymbolAddress((void**)&pw2t, g_w2t);

    cudaFuncSetAttribute(attn_f16_kernel,
                         cudaFuncAttributeMaxDynamicSharedMemorySize, (int)ATTN_SMEM);
    cudaFuncSetAttribute(f16_gemm<0>,
                         cudaFuncAttributeMaxDynamicSharedMemorySize, (int)GEMM_SMEM);
    cudaFuncSetAttribute(f16_gemm<1>,
                         cudaFuncAttributeMaxDynamicSharedMemorySize, (int)GEMM_SMEM);
    cudaFuncSetAttribute(f16_gemm<2>,
                         cudaFuncAttributeMaxDynamicSharedMemorySize, (int)GEMM_SMEM);

    wtrans_all_kernel<<<dim3(64, 64, 10), dim3(32, 8)>>>(
        Wk, Wv, Wo, W1, W2, pwkt, pwvt, pwot, pw1t, pw2t);

    add_pe_kernel<<<(BSD / 4 + 255) / 256, 256>>>(
        (const float4*)qe, (const float4*)qa, (const float4*)pe,
        (float4*)px, pxh, pyh);

    dim3 g512 (DD / 128, MTOK / 128, 1);   // (4, 128)
    dim3 g512z(DD / 128, MTOK / 128, 2);   // merged q & v
    dim3 gff  (FFD / 128, MTOK / 128, 1);  // (16, 128)
    dim3 gattn(SS / 64, BB * HH);          // (8, 256)

    for (int i = 0; i < NBLK; i++) {
        const __half* wkt = pwkt + (size_t)i * DD * DD;
        const __half* wvt = pwvt + (size_t)i * DD * DD;
        const __half* wot = pwot + (size_t)i * DD * DD;
        const __half* w1t = pw1t + (size_t)i * DD * FFD;
        const __half* w2t = pw2t + (size_t)i * FFD * DD;

        // merged: z=0 -> q = x@Wk + bk (fp16) ; z=1 -> v = y@Wv + bv (fp16)
        f16_gemm<2><<<g512z, 256, GEMM_SMEM>>>(
            pxh, wkt, bk + i * DD, pqh,
            pyh, wvt, bv + i * DD, pvh, MTOK, DD, DD);
        // attention (fp16 in/out)
        attn_f16_kernel<<<gattn, 128, ATTN_SMEM>>>(pqh, pvh, fr, pah);
        // proj = ah @ Wo + bo -> pt (fp32)
        f16_gemm<0><<<g512, 256, GEMM_SMEM>>>(
            pah, wot, bo + i * DD, pt,
            pah, wot, bo + i * DD, pt, MTOK, DD, DD);
        // x = LN(x + proj); xh = fp16(x)
        ln_res_kernel<<<MTOK, 128>>>(px, pt, g1 + i * DD, be1 + i * DD, px, pxh);
        // hidden = relu(x @ W1 + bf1) -> fp16 fh
        f16_gemm<1><<<gff, 256, GEMM_SMEM>>>(
            pxh, w1t, bf1 + i * FFD, pfh,
            pxh, w1t, bf1 + i * FFD, pfh, MTOK, FFD, DD);
        // ffn = fh @ W2 + bf2 -> pt (fp32)
        f16_gemm<0><<<g512, 256, GEMM_SMEM>>>(
            pfh, w2t, bf2 + i * DD, pt,
            pfh, w2t, bf2 + i * DD, pt, MTOK, DD, FFD);
        // x = LN(x + ffn)
        float*  dst = (i == NBLK - 1) ? out : px;
        __half* dh  = (i == NBLK - 1) ? nullptr : pxh;
        ln_res_kernel<<<MTOK, 128>>>(px, pt, g2 + i * DD, be2 + i * DD, dst, dh);
    }
}

// round 16
// speedup vs baseline: 1.1265x; 1.0702x over previous
#include <cuda_runtime.h>
#include <cuda_fp16.h>
#include <math.h>
#include <stdint.h>

// Problem constants
#define BB   32
#define SS   512
#define DD   512
#define HH   8
#define DKK  64
#define FFD  2048
#define NBLK 2
#define MTOK (BB*SS)            // 16384 token rows
#define BSD  (BB*SS*DD)         // 8388608
#define BSF  (BB*SS*FFD)        // 33554432

// Scratch (static device globals — no allocation allowed)
__device__ float  g_x[BSD];          // residual stream (fp32)
__device__ float  g_t[BSD];          // fp32 temp (proj / ffn out)
__device__ __half g_qh[BSD];         // q (fp16, attn input)
__device__ __half g_vh[BSD];         // v (fp16, attn input)
__device__ __half g_xh[BSD];         // fp16 activations
__device__ __half g_yh[BSD];
__device__ __half g_ah[BSD];         // attn output (fp16)
__device__ __half g_fh[BSF];         // ffn hidden (fp16)
__device__ __half g_wkt[NBLK*DD*DD]; // transposed fp16 weights [N][K]
__device__ __half g_wvt[NBLK*DD*DD];
__device__ __half g_wot[NBLK*DD*DD];
__device__ __half g_w1t[NBLK*DD*FFD];
__device__ __half g_w2t[NBLK*FFD*DD];

// ---------------------------------------------------------------------------
// helpers
// ---------------------------------------------------------------------------
__device__ __forceinline__ void mma_f16(float c[4],
                                        uint32_t a0, uint32_t a1,
                                        uint32_t a2, uint32_t a3,
                                        uint32_t b0, uint32_t b1)
{
    asm volatile(
        "mma.sync.aligned.m16n8k16.row.col.f32.f16.f16.f32 "
        "{%0,%1,%2,%3}, {%4,%5,%6,%7}, {%8,%9}, {%0,%1,%2,%3};"
        : "+f"(c[0]), "+f"(c[1]), "+f"(c[2]), "+f"(c[3])
        : "r"(a0), "r"(a1), "r"(a2), "r"(a3), "r"(b0), "r"(b1));
}
__device__ __forceinline__ void ldsm_x4(uint32_t r[4], uint32_t addr) {
    asm volatile("ldmatrix.sync.aligned.m8n8.x4.shared.b16 {%0,%1,%2,%3}, [%4];"
        : "=r"(r[0]), "=r"(r[1]), "=r"(r[2]), "=r"(r[3]) : "r"(addr));
}
__device__ __forceinline__ void ldsm_x2(uint32_t r[2], uint32_t addr) {
    asm volatile("ldmatrix.sync.aligned.m8n8.x2.shared.b16 {%0,%1}, [%2];"
        : "=r"(r[0]), "=r"(r[1]) : "r"(addr));
}
__device__ __forceinline__ void cp_async16(uint32_t smem_addr, const void* gptr) {
    asm volatile("cp.async.cg.shared.global [%0], [%1], 16;"
                 :: "r"(smem_addr), "l"(gptr));
}
__device__ __forceinline__ void cp_commit() {
    asm volatile("cp.async.commit_group;");
}
template<int N>
__device__ __forceinline__ void cp_wait() {
    asm volatile("cp.async.wait_group %0;" :: "n"(N));
}
__device__ __forceinline__ uint32_t pack_h2(__half lo, __half hi) {
    __half2 h; h.x = lo; h.y = hi;
    return *(uint32_t*)&h;
}
__device__ __forceinline__ uint32_t h2u(__half2 h) {
    return *(uint32_t*)&h;
}

// ---------------------------------------------------------------------------
// One-shot weight transpose + fp16 convert for ALL weights.
// W[K][N] fp32 -> Wt[N][K] fp16.  z in [0,10): (matrix, block) pairs.
// ---------------------------------------------------------------------------
__global__ void wtrans_all_kernel(
    const float* __restrict__ Wk, const float* __restrict__ Wv,
    const float* __restrict__ Wo, const float* __restrict__ W1,
    const float* __restrict__ W2,
    __half* __restrict__ twk, __half* __restrict__ twv,
    __half* __restrict__ two, __half* __restrict__ tw1,
    __half* __restrict__ tw2)
{
    const int z   = blockIdx.z;
    const int blk = z & 1;
    const float* W; __half* T; int K, N;
    switch (z >> 1) {
        case 0: W = Wk + (size_t)blk * DD * DD;  T = twk + (size_t)blk * DD * DD;  K = DD;  N = DD;  break;
        case 1: W = Wv + (size_t)blk * DD * DD;  T = twv + (size_t)blk * DD * DD;  K = DD;  N = DD;  break;
        case 2: W = Wo + (size_t)blk * DD * DD;  T = two + (size_t)blk * DD * DD;  K = DD;  N = DD;  break;
        case 3: W = W1 + (size_t)blk * DD * FFD; T = tw1 + (size_t)blk * DD * FFD; K = DD;  N = FFD; break;
        default:W = W2 + (size_t)blk * FFD * DD; T = tw2 + (size_t)blk * FFD * DD; K = FFD; N = DD;  break;
    }
    const int n0 = blockIdx.x * 32;
    const int k0 = blockIdx.y * 32;
    if (n0 >= N || k0 >= K) return;

    __shared__ float t[32][33];
    const int tx = threadIdx.x, ty = threadIdx.y;
    for (int j = ty; j < 32; j += 8)
        t[j][tx] = W[(size_t)(k0 + j) * N + n0 + tx];
    __syncthreads();
    for (int j = ty; j < 32; j += 8)
        T[(size_t)(n0 + j) * K + k0 + tx] = __float2half_rn(t[tx][j]);
}

// ---------------------------------------------------------------------------
// x = qe+pe (fp32 residual) + fp16 copies xh, yh of both streams
// ---------------------------------------------------------------------------
__global__ void add_pe_kernel(const float4* __restrict__ qe,
                              const float4* __restrict__ qa,
                              const float4* __restrict__ pe,
                              float4* __restrict__ x,
                              __half* __restrict__ xh, __half* __restrict__ yh)
{
    int i = blockIdx.x * blockDim.x + threadIdx.x;
    const int n4 = BSD / 4;
    if (i >= n4) return;
    int pi = i & (SS * DD / 4 - 1);
    float4 p = pe[pi];
    float4 a = qe[i];
    a.x += p.x; a.y += p.y; a.z += p.z; a.w += p.w;
    x[i] = a;
    ((__half2*)(xh + 4 * (size_t)i))[0] = __floats2half2_rn(a.x, a.y);
    ((__half2*)(xh + 4 * (size_t)i))[1] = __floats2half2_rn(a.z, a.w);
    float4 b = qa[i];
    b.x += p.x; b.y += p.y; b.z += p.z; b.w += p.w;
    ((__half2*)(yh + 4 * (size_t)i))[0] = __floats2half2_rn(b.x, b.y);
    ((__half2*)(yh + 4 * (size_t)i))[1] = __floats2half2_rn(b.z, b.w);
}

// ---------------------------------------------------------------------------
// FP16 tensor-core GEMM: C[M,N] = A[M,K] @ Wt[N,K]^T + bias[N]
// 256 threads (2x4 warps, 64x32 warp tiles), BK=32, 3-stage cp.async,
// fragments via ldmatrix (8 LDSM vs 24 LDS per k-chunk per warp).
// MODE 0: fp32 out. MODE 1: ReLU + fp16 out. MODE 2: fp16 out.
// ---------------------------------------------------------------------------
#define HST 40
#define HTILE (128 * HST)
#define STGH (2 * HTILE)
#define NSTG 3
#define GEMM_SMEM (NSTG * STGH * sizeof(__half))   // 61440 B

template<int MODE>
__global__ void __launch_bounds__(256, 2) f16_gemm(
    const __half* __restrict__ A0, const __half* __restrict__ W0,
    const float* __restrict__ b0p, void* __restrict__ C0,
    const __half* __restrict__ A1, const __half* __restrict__ W1p,
    const float* __restrict__ b1p, void* __restrict__ C1,
    int M, int N, int K)
{
    extern __shared__ __half smh[];

    const __half* A    = blockIdx.z ? A1  : A0;
    const __half* W    = blockIdx.z ? W1p : W0;
    const float*  bias = blockIdx.z ? b1p : b0p;
    void*         C    = blockIdx.z ? C1  : C0;

    const int tid  = threadIdx.x;
    const int lane = tid & 31;
    const int wid  = tid >> 5;
    const int wm   = wid & 1;
    const int wn   = wid >> 1;
    const int grp  = lane >> 2;
    const int tig  = lane & 3;
    const int m0   = blockIdx.y * 128;
    const int n0   = blockIdx.x * 128;

    const uint32_t sS = (uint32_t)__cvta_generic_to_shared(smh);

    const int l_row = tid >> 1;
    const int l_h0  = (tid & 1) * 16;

    // ldmatrix per-lane base addresses (bytes)
    const uint32_t a_lm = sS + (uint32_t)(((wm * 64 + (lane & 15)) * HST
                                           + ((lane >> 4) << 3)) * 2);
    const uint32_t b_lm = sS + (uint32_t)(HTILE * 2)
                        + (uint32_t)(((wn * 32 + (lane & 7)) * HST
                                           + (((lane >> 3) & 1) << 3)) * 2);

    float acc[4][4][4];
#pragma unroll
    for (int i = 0; i < 4; i++)
#pragma unroll
        for (int j = 0; j < 4; j++)
#pragma unroll
            for (int r = 0; r < 4; r++) acc[i][j][r] = 0.f;

    const int nk = K >> 5;

    auto load_stage = [&](int stg, int k0) {
        const uint32_t sb = sS + (uint32_t)(stg * STGH * 2);
        {
            const __half* ga = A + (size_t)(m0 + l_row) * K + k0 + l_h0;
            uint32_t da = sb + (uint32_t)((l_row * HST + l_h0) * 2);
            cp_async16(da,      ga);
            cp_async16(da + 16, ga + 8);
        }
        {
            const __half* gb = W + (size_t)(n0 + l_row) * K + k0 + l_h0;
            uint32_t db = sb + (uint32_t)((HTILE + l_row * HST + l_h0) * 2);
            cp_async16(db,      gb);
            cp_async16(db + 16, gb + 8);
        }
    };

    load_stage(0, 0);
    cp_commit();
    load_stage(1, 32);
    cp_commit();

    for (int kt = 0; kt < nk; kt++) {
        if (kt + NSTG - 1 < nk) {
            int s = kt + NSTG - 1;
            load_stage(s % NSTG, s * 32);
        }
        cp_commit();
        cp_wait<NSTG - 1>();
        __syncthreads();

        const uint32_t stq = (uint32_t)((kt % NSTG) * STGH * 2);

#pragma unroll
        for (int kk = 0; kk < 32; kk += 16) {
            uint32_t af[4][4];
            uint32_t bf[4][2];
#pragma unroll
            for (int mt = 0; mt < 4; mt++)
                ldsm_x4(af[mt], a_lm + stq + (uint32_t)((mt * 16 * HST + kk) * 2));
#pragma unroll
            for (int nt = 0; nt < 4; nt++)
                ldsm_x2(bf[nt], b_lm + stq + (uint32_t)((nt * 8 * HST + kk) * 2));
#pragma unroll
            for (int mt = 0; mt < 4; mt++)
#pragma unroll
                for (int nt = 0; nt < 4; nt++)
                    mma_f16(acc[mt][nt],
                            af[mt][0], af[mt][1], af[mt][2], af[mt][3],
                            bf[nt][0], bf[nt][1]);
        }
        __syncthreads();
    }

#pragma unroll
    for (int mt = 0; mt < 4; mt++) {
#pragma unroll
        for (int nt = 0; nt < 4; nt++) {
            int row = m0 + wm * 64 + mt * 16 + grp;
            int col = n0 + wn * 32 + nt * 8 + tig * 2;
            float bb0 = bias[col], bb1 = bias[col + 1];
            float v0 = acc[mt][nt][0] + bb0;
            float v1 = acc[mt][nt][1] + bb1;
            float v2 = acc[mt][nt][2] + bb0;
            float v3 = acc[mt][nt][3] + bb1;
            if (MODE == 0) {
                float* Cf = (float*)C;
                *(float2*)(Cf + (size_t)row * N + col)       = make_float2(v0, v1);
                *(float2*)(Cf + (size_t)(row + 8) * N + col) = make_float2(v2, v3);
            } else {
                if (MODE == 1) {
                    v0 = fmaxf(v0, 0.f); v1 = fmaxf(v1, 0.f);
                    v2 = fmaxf(v2, 0.f); v3 = fmaxf(v3, 0.f);
                }
                __half* Ch = (__half*)C;
                *(__half2*)(Ch + (size_t)row * N + col)       = __floats2half2_rn(v0, v1);
                *(__half2*)(Ch + (size_t)(row + 8) * N + col) = __floats2half2_rn(v2, v3);
            }
        }
    }
}

// ---------------------------------------------------------------------------
// FP16 flash attention (R15: 64-row q-tiles, 128 threads, double-buffered
// cp.async K/V). Smem: Qs + 2x Ks + 2x Vs [64][72] halves (46080 B).
// ---------------------------------------------------------------------------
#define APADH 72
#define ATILE (64 * APADH)
#define ATTN_SMEM (5 * ATILE * sizeof(__half))

__global__ void __launch_bounds__(128, 4) attn_f16_kernel(
    const __half* __restrict__ Q, const __half* __restrict__ V,
    const float* __restrict__ FR, __half* __restrict__ AH)
{
    extern __shared__ __half smh[];
    __half* Qs = smh;                        // [64][APADH]

    const int qt   = gridDim.x - 1 - blockIdx.x;   // heavy-first
    const int bh   = blockIdx.y;
    const int b    = bh >> 3;
    const int h    = bh & 7;
    const int tid  = threadIdx.x;
    const int lane = tid & 31;
    const int w    = tid >> 5;
    const int grp  = lane >> 2;
    const int tig  = lane & 3;
    const int q0   = qt * 64;
    const size_t base = (size_t)b * SS * DD + (size_t)h * DKK;

    const uint32_t sB = (uint32_t)__cvta_generic_to_shared(smh);
    const int l_r  = tid >> 3;
    const int l_c8 = (tid & 7) * 8;

    auto load_kv = [&](int buf, int kt) {
        const uint32_t kb = sB + (uint32_t)((1 + 2 * buf) * ATILE * 2);
        const uint32_t vb = sB + (uint32_t)((2 + 2 * buf) * ATILE * 2);
#pragma unroll
        for (int j = 0; j < 4; j++) {
            int r = l_r + 16 * j;
            const __half* gk = Q + base + (size_t)(kt * 64 + r) * DD + l_c8;
            const __half* gv = V + base + (size_t)(kt * 64 + r) * DD + l_c8;
            uint32_t off = (uint32_t)((r * APADH + l_c8) * 2);
            cp_async16(kb + off, gk);
            cp_async16(vb + off, gv);
        }
    };

#pragma unroll
    for (int j = 0; j < 4; j++) {
        int idx = j * 128 + tid;
        int r   = idx >> 3;
        int c8  = (idx & 7) * 8;
        *(float4*)(Qs + r * APADH + c8) =
            *(const float4*)(Q + base + (size_t)(q0 + r) * DD + c8);
    }

    const int rg0 = q0 + w * 16 + grp;
    const float frs0 = FR[b * SS + rg0]     * 0.125f;
    const float frs1 = FR[b * SS + rg0 + 8] * 0.125f;

    float m0 = -3.0e38f, m1 = -3.0e38f, l0 = 0.f, l1 = 0.f;
    float o[8][4];
#pragma unroll
    for (int nt = 0; nt < 8; nt++)
#pragma unroll
        for (int r = 0; r < 4; r++) o[nt][r] = 0.f;

    load_kv(0, 0);
    cp_commit();

    for (int kt = 0; kt <= qt; kt++) {
        if (kt + 1 <= qt) load_kv((kt + 1) & 1, kt + 1);
        cp_commit();
        cp_wait<1>();
        __syncthreads();

        const __half* Ks = smh + (1 + 2 * (kt & 1)) * ATILE;
        const __half* Vs = smh + (2 + 2 * (kt & 1)) * ATILE;

        float sc[8][4];
#pragma unroll
        for (int nt = 0; nt < 8; nt++)
#pragma unroll
            for (int r = 0; r < 4; r++) sc[nt][r] = 0.f;

        const int mr = w * 16 + grp;
#pragma unroll
        for (int kc = 0; kc < 4; kc++) {
            const int k0 = kc * 16;
            uint32_t a0 = *(const uint32_t*)(Qs + (mr    ) * APADH + k0 + 2 * tig    );
            uint32_t a1 = *(const uint32_t*)(Qs + (mr + 8) * APADH + k0 + 2 * tig    );
            uint32_t a2 = *(const uint32_t*)(Qs + (mr    ) * APADH + k0 + 2 * tig + 8);
            uint32_t a3 = *(const uint32_t*)(Qs + (mr + 8) * APADH + k0 + 2 * tig + 8);
#pragma unroll
            for (int nt = 0; nt < 8; nt++) {
                int nc = nt * 8 + grp;
                uint32_t b0 = *(const uint32_t*)(Ks + nc * APADH + k0 + 2 * tig    );
                uint32_t b1 = *(const uint32_t*)(Ks + nc * APADH + k0 + 2 * tig + 8);
                mma_f16(sc[nt], a0, a1, a2, a3, b0, b1);
            }
        }

        const bool diag = (kt == qt);
        float mx0 = -3.0e38f, mx1 = -3.0e38f;
#pragma unroll
        for (int nt = 0; nt < 8; nt++) {
            int cg = kt * 64 + nt * 8 + 2 * tig;
            float s0 = sc[nt][0] * frs0;
            float s1 = sc[nt][1] * frs0;
            float s2 = sc[nt][2] * frs1;
            float s3 = sc[nt][3] * frs1;
            if (diag) {
                if (cg     >= rg0)     s0 = -1e30f;
                if (cg + 1 >= rg0)     s1 = -1e30f;
                if (cg     >= rg0 + 8) s2 = -1e30f;
                if (cg + 1 >= rg0 + 8) s3 = -1e30f;
            }
            sc[nt][0] = s0; sc[nt][1] = s1; sc[nt][2] = s2; sc[nt][3] = s3;
            mx0 = fmaxf(mx0, fmaxf(s0, s1));
            mx1 = fmaxf(mx1, fmaxf(s2, s3));
        }
        mx0 = fmaxf(mx0, __shfl_xor_sync(0xffffffffu, mx0, 1));
        mx0 = fmaxf(mx0, __shfl_xor_sync(0xffffffffu, mx0, 2));
        mx1 = fmaxf(mx1, __shfl_xor_sync(0xffffffffu, mx1, 1));
        mx1 = fmaxf(mx1, __shfl_xor_sync(0xffffffffu, mx1, 2));

        float mn0 = fmaxf(m0, mx0);
        float mn1 = fmaxf(m1, mx1);
        float al0 = __expf(m0 - mn0);
        float al1 = __expf(m1 - mn1);
        m0 = mn0; m1 = mn1;

        float su0 = 0.f, su1 = 0.f;
        uint32_t pu[8][2];
#pragma unroll
        for (int nt = 0; nt < 8; nt++) {
            float p0 = __expf(sc[nt][0] - mn0);
            float p1 = __expf(sc[nt][1] - mn0);
            float p2 = __expf(sc[nt][2] - mn1);
            float p3 = __expf(sc[nt][3] - mn1);
            su0 += p0 + p1;
            su1 += p2 + p3;
            pu[nt][0] = h2u(__floats2half2_rn(p0, p1));
            pu[nt][1] = h2u(__floats2half2_rn(p2, p3));
        }
        su0 += __shfl_xor_sync(0xffffffffu, su0, 1);
        su0 += __shfl_xor_sync(0xffffffffu, su0, 2);
        su1 += __shfl_xor_sync(0xffffffffu, su1, 1);
        su1 += __shfl_xor_sync(0xffffffffu, su1, 2);
        l0 = l0 * al0 + su0;
        l1 = l1 * al1 + su1;
#pragma unroll
        for (int nt = 0; nt < 8; nt++) {
            o[nt][0] *= al0; o[nt][1] *= al0;
            o[nt][2] *= al1; o[nt][3] *= al1;
        }

#pragma unroll
        for (int j = 0; j < 4; j++) {
            const int k0 = j * 16;
            uint32_t a0 = pu[2 * j    ][0];
            uint32_t a1 = pu[2 * j    ][1];
            uint32_t a2 = pu[2 * j + 1][0];
            uint32_t a3 = pu[2 * j + 1][1];
#pragma unroll
            for (int nt = 0; nt < 8; nt++) {
                int n = nt * 8 + grp;
                uint32_t b0 = pack_h2(Vs[(k0 + 2 * tig    ) * APADH + n],
                                      Vs[(k0 + 2 * tig + 1) * APADH + n]);
                uint32_t b1 = pack_h2(Vs[(k0 + 2 * tig + 8) * APADH + n],
                                      Vs[(k0 + 2 * tig + 9) * APADH + n]);
                mma_f16(o[nt], a0, a1, a2, a3, b0, b1);
            }
        }
        __syncthreads();
    }

    float inv0 = (rg0 == 0) ? 0.f : (1.0f / l0);
    float inv1 = 1.0f / l1;
#pragma unroll
    for (int nt = 0; nt < 8; nt++) {
        int col = nt * 8 + tig * 2;
        *(__half2*)(AH + base + (size_t)(rg0    ) * DD + col) =
            __floats2half2_rn(o[nt][0] * inv0, o[nt][1] * inv0);
        *(__half2*)(AH + base + (size_t)(rg0 + 8) * DD + col) =
            __floats2half2_rn(o[nt][2] * inv1, o[nt][3] * inv1);
    }
}

// ---------------------------------------------------------------------------
// out = LayerNorm(x + r)*g + be; optional fp16 copy outh
// ---------------------------------------------------------------------------
__global__ void __launch_bounds__(128) ln_res_kernel(
    const float* __restrict__ x, const float* __restrict__ r,
    const float* __restrict__ g, const float* __restrict__ be,
    float* __restrict__ out, __half* __restrict__ outh)
{
    int row = blockIdx.x;
    int tid = threadIdx.x;
    const float4* xp = (const float4*)(x + (size_t)row * DD);
    const float4* rp = (const float4*)(r + (size_t)row * DD);
    float4 v = xp[tid], w = rp[tid];
    v.x += w.x; v.y += w.y; v.z += w.z; v.w += w.w;
    float s  = v.x + v.y + v.z + v.w;
    float ss = v.x * v.x + v.y * v.y + v.z * v.z + v.w * v.w;
#pragma unroll
    for (int ofs = 16; ofs > 0; ofs >>= 1) {
        s  += __shfl_xor_sync(0xffffffffu, s,  ofs);
        ss += __shfl_xor_sync(0xffffffffu, ss, ofs);
    }
    __shared__ float sb[4], ssb[4];
    int wid = tid >> 5;
    if ((tid & 31) == 0) { sb[wid] = s; ssb[wid] = ss; }
    __syncthreads();
    s  = sb[0]  + sb[1]  + sb[2]  + sb[3];
    ss = ssb[0] + ssb[1] + ssb[2] + ssb[3];
    float mean = s * (1.0f / DD);
    float var  = ss * (1.0f / DD) - mean * mean;
    float rs   = rsqrtf(var + 1e-5f);
    float4 gv = ((const float4*)g)[tid];
    float4 bv = ((const float4*)be)[tid];
    float4 o4;
    o4.x = (v.x - mean) * rs * gv.x + bv.x;
    o4.y = (v.y - mean) * rs * gv.y + bv.y;
    o4.z = (v.z - mean) * rs * gv.z + bv.z;
    o4.w = (v.w - mean) * rs * gv.w + bv.w;
    ((float4*)(out + (size_t)row * DD))[tid] = o4;
    if (outh) {
        size_t e = (size_t)row * DD + tid * 4;
        ((__half2*)(outh + e))[0] = __floats2half2_rn(o4.x, o4.y);
        ((__half2*)(outh + e))[1] = __floats2half2_rn(o4.z, o4.w);
    }
}

// ---------------------------------------------------------------------------
extern "C" void kernel_launch(void* const* d_in, const int* in_sizes, int n_in,
                              void* d_out, int out_size)
{
    const float* qe  = (const float*)d_in[0];
    const float* qa  = (const float*)d_in[1];
    const float* fr  = (const float*)d_in[2];
    const float* pe  = (const float*)d_in[3];
    const float* Wk  = (const float*)d_in[4];
    const float* bk  = (const float*)d_in[5];
    const float* Wv  = (const float*)d_in[6];
    const float* bv  = (const float*)d_in[7];
    const float* Wo  = (const float*)d_in[8];
    const float* bo  = (const float*)d_in[9];
    const float* g1  = (const float*)d_in[10];
    const float* be1 = (const float*)d_in[11];
    const float* W1  = (const float*)d_in[12];
    const float* bf1 = (const float*)d_in[13];
    const float* W2  = (const float*)d_in[14];
    const float* bf2 = (const float*)d_in[15];
    const float* g2  = (const float*)d_in[16];
    const float* be2 = (const float*)d_in[17];
    float* out = (float*)d_out;

    float  *px, *pt;
    __half *pqh, *pvh, *pxh, *pyh, *pah, *pfh, *pwkt, *pwvt, *pwot, *pw1t, *pw2t;
    cudaGetSymbolAddress((void**)&px,   g_x);
    cudaGetSymbolAddress((void**)&pt,   g_t);
    cudaGetSymbolAddress((void**)&pqh,  g_qh);
    cudaGetSymbolAddress((void**)&pvh,  g_vh);
    cudaGetSymbolAddress((void**)&pxh,  g_xh);
    cudaGetSymbolAddress((void**)&pyh,  g_yh);
    cudaGetSymbolAddress((void**)&pah,  g_ah);
    cudaGetSymbolAddress((void**)&pfh,  g_fh);
    cudaGetSymbolAddress((void**)&pwkt, g_wkt);
    cudaGetSymbolAddress((void**)&pwvt, g_wvt);
    cudaGetSymbolAddress((void**)&pwot, g_wot);
    cudaGetSymbolAddress((void**)&pw1t, g_w1t);
    cudaGetSymbolAddress((void**)&pw2t, g_w2t);

    cudaFuncSetAttribute(attn_f16_kernel,
                         cudaFuncAttributeMaxDynamicSharedMemorySize, (int)ATTN_SMEM);
    cudaFuncSetAttribute(f16_gemm<0>,
                         cudaFuncAttributeMaxDynamicSharedMemorySize, (int)GEMM_SMEM);
    cudaFuncSetAttribute(f16_gemm<1>,
                         cudaFuncAttributeMaxDynamicSharedMemorySize, (int)GEMM_SMEM);
    cudaFuncSetAttribute(f16_gemm<2>,
                         cudaFuncAttributeMaxDynamicSharedMemorySize, (int)GEMM_SMEM);

    wtrans_all_kernel<<<dim3(64, 64, 10), dim3(32, 8)>>>(
        Wk, Wv, Wo, W1, W2, pwkt, pwvt, pwot, pw1t, pw2t);

    add_pe_kernel<<<(BSD / 4 + 255) / 256, 256>>>(
        (const float4*)qe, (const float4*)qa, (const float4*)pe,
        (float4*)px, pxh, pyh);

    dim3 g512 (DD / 128, MTOK / 128, 1);   // (4, 128)
    dim3 g512z(DD / 128, MTOK / 128, 2);   // merged q & v
    dim3 gff  (FFD / 128, MTOK / 128, 1);  // (16, 128)
    dim3 gattn(SS / 64, BB * HH);          // (8, 256)

    for (int i = 0; i < NBLK; i++) {
        const __half* wkt = pwkt + (size_t)i * DD * DD;
        const __half* wvt = pwvt + (size_t)i * DD * DD;
        const __half* wot = pwot + (size_t)i * DD * DD;
        const __half* w1t = pw1t + (size_t)i * DD * FFD;
        const __half* w2t = pw2t + (size_t)i * FFD * DD;

        // merged: z=0 -> q = x@Wk + bk (fp16) ; z=1 -> v = y@Wv + bv (fp16)
        f16_gemm<2><<<g512z, 256, GEMM_SMEM>>>(
            pxh, wkt, bk + i * DD, pqh,
            pyh, wvt, bv + i * DD, pvh, MTOK, DD, DD);
        // attention (fp16 in/out)
        attn_f16_kernel<<<gattn, 128, ATTN_SMEM>>>(pqh, pvh, fr, pah);
        // proj = ah @ Wo + bo -> pt (fp32)
        f16_gemm<0><<<g512, 256, GEMM_SMEM>>>(
            pah, wot, bo + i * DD, pt,
            pah, wot, bo + i * DD, pt, MTOK, DD, DD);
        // x = LN(x + proj); xh = fp16(x)
        ln_res_kernel<<<MTOK, 128>>>(px, pt, g1 + i * DD, be1 + i * DD, px, pxh);
        // hidden = relu(x @ W1 + bf1) -> fp16 fh
        f16_gemm<1><<<gff, 256, GEMM_SMEM>>>(
            pxh, w1t, bf1 + i * FFD, pfh,
            pxh, w1t, bf1 + i * FFD, pfh, MTOK, FFD, DD);
        // ffn = fh @ W2 + bf2 -> pt (fp32)
        f16_gemm<0><<<g512, 256, GEMM_SMEM>>>(
            pfh, w2t, bf2 + i * DD, pt,
            pfh, w2t, bf2 + i * DD, pt, MTOK, DD, FFD);
        // x = LN(x + ffn)
        float*  dst = (i == NBLK - 1) ? out : px;
        __half* dh  = (i == NBLK - 1) ? nullptr : pxh;
        ln_res_kernel<<<MTOK, 128>>>(px, pt, g2 + i * DD, be2 + i * DD, dst, dh);
    }
}

// round 17
// speedup vs baseline: 1.1452x; 1.0166x over previous
#include <cuda_runtime.h>
#include <cuda_fp16.h>
#include <math.h>
#include <stdint.h>

// Problem constants
#define BB   32
#define SS   512
#define DD   512
#define HH   8
#define DKK  64
#define FFD  2048
#define NBLK 2
#define MTOK (BB*SS)            // 16384 token rows
#define BSD  (BB*SS*DD)         // 8388608
#define BSF  (BB*SS*FFD)        // 33554432

// Scratch (static device globals — no allocation allowed)
__device__ float  g_x[BSD];          // residual stream (fp32)
__device__ float  g_t[BSD];          // fp32 temp (proj / ffn out)
__device__ __half g_qh[BSD];         // q (fp16, attn input)
__device__ __half g_vh[BSD];         // v (fp16, attn input)
__device__ __half g_xh[BSD];         // fp16 activations
__device__ __half g_yh[BSD];
__device__ __half g_ah[BSD];         // attn output (fp16)
__device__ __half g_fh[BSF];         // ffn hidden (fp16)
__device__ __half g_wkt[NBLK*DD*DD]; // transposed fp16 weights [N][K]
__device__ __half g_wvt[NBLK*DD*DD];
__device__ __half g_wot[NBLK*DD*DD];
__device__ __half g_w1t[NBLK*DD*FFD];
__device__ __half g_w2t[NBLK*FFD*DD];

// ---------------------------------------------------------------------------
// helpers
// ---------------------------------------------------------------------------
__device__ __forceinline__ void mma_f16(float c[4],
                                        uint32_t a0, uint32_t a1,
                                        uint32_t a2, uint32_t a3,
                                        uint32_t b0, uint32_t b1)
{
    asm volatile(
        "mma.sync.aligned.m16n8k16.row.col.f32.f16.f16.f32 "
        "{%0,%1,%2,%3}, {%4,%5,%6,%7}, {%8,%9}, {%0,%1,%2,%3};"
        : "+f"(c[0]), "+f"(c[1]), "+f"(c[2]), "+f"(c[3])
        : "r"(a0), "r"(a1), "r"(a2), "r"(a3), "r"(b0), "r"(b1));
}
__device__ __forceinline__ void ldsm_x4(uint32_t r[4], uint32_t addr) {
    asm volatile("ldmatrix.sync.aligned.m8n8.x4.shared.b16 {%0,%1,%2,%3}, [%4];"
        : "=r"(r[0]), "=r"(r[1]), "=r"(r[2]), "=r"(r[3]) : "r"(addr));
}
__device__ __forceinline__ void ldsm_x2(uint32_t r[2], uint32_t addr) {
    asm volatile("ldmatrix.sync.aligned.m8n8.x2.shared.b16 {%0,%1}, [%2];"
        : "=r"(r[0]), "=r"(r[1]) : "r"(addr));
}
__device__ __forceinline__ void ldsm_x4t(uint32_t r[4], uint32_t addr) {
    asm volatile("ldmatrix.sync.aligned.m8n8.x4.trans.shared.b16 {%0,%1,%2,%3}, [%4];"
        : "=r"(r[0]), "=r"(r[1]), "=r"(r[2]), "=r"(r[3]) : "r"(addr));
}
__device__ __forceinline__ void cp_async16(uint32_t smem_addr, const void* gptr) {
    asm volatile("cp.async.cg.shared.global [%0], [%1], 16;"
                 :: "r"(smem_addr), "l"(gptr));
}
__device__ __forceinline__ void cp_commit() {
    asm volatile("cp.async.commit_group;");
}
template<int N>
__device__ __forceinline__ void cp_wait() {
    asm volatile("cp.async.wait_group %0;" :: "n"(N));
}
__device__ __forceinline__ uint32_t h2u(__half2 h) {
    return *(uint32_t*)&h;
}

// ---------------------------------------------------------------------------
// One-shot weight transpose + fp16 convert for ALL weights.
// ---------------------------------------------------------------------------
__global__ void wtrans_all_kernel(
    const float* __restrict__ Wk, const float* __restrict__ Wv,
    const float* __restrict__ Wo, const float* __restrict__ W1,
    const float* __restrict__ W2,
    __half* __restrict__ twk, __half* __restrict__ twv,
    __half* __restrict__ two, __half* __restrict__ tw1,
    __half* __restrict__ tw2)
{
    const int z   = blockIdx.z;
    const int blk = z & 1;
    const float* W; __half* T; int K, N;
    switch (z >> 1) {
        case 0: W = Wk + (size_t)blk * DD * DD;  T = twk + (size_t)blk * DD * DD;  K = DD;  N = DD;  break;
        case 1: W = Wv + (size_t)blk * DD * DD;  T = twv + (size_t)blk * DD * DD;  K = DD;  N = DD;  break;
        case 2: W = Wo + (size_t)blk * DD * DD;  T = two + (size_t)blk * DD * DD;  K = DD;  N = DD;  break;
        case 3: W = W1 + (size_t)blk * DD * FFD; T = tw1 + (size_t)blk * DD * FFD; K = DD;  N = FFD; break;
        default:W = W2 + (size_t)blk * FFD * DD; T = tw2 + (size_t)blk * FFD * DD; K = FFD; N = DD;  break;
    }
    const int n0 = blockIdx.x * 32;
    const int k0 = blockIdx.y * 32;
    if (n0 >= N || k0 >= K) return;

    __shared__ float t[32][33];
    const int tx = threadIdx.x, ty = threadIdx.y;
    for (int j = ty; j < 32; j += 8)
        t[j][tx] = W[(size_t)(k0 + j) * N + n0 + tx];
    __syncthreads();
    for (int j = ty; j < 32; j += 8)
        T[(size_t)(n0 + j) * K + k0 + tx] = __float2half_rn(t[tx][j]);
}

// ---------------------------------------------------------------------------
// x = qe+pe (fp32 residual) + fp16 copies xh, yh of both streams
// ---------------------------------------------------------------------------
__global__ void add_pe_kernel(const float4* __restrict__ qe,
                              const float4* __restrict__ qa,
                              const float4* __restrict__ pe,
                              float4* __restrict__ x,
                              __half* __restrict__ xh, __half* __restrict__ yh)
{
    int i = blockIdx.x * blockDim.x + threadIdx.x;
    const int n4 = BSD / 4;
    if (i >= n4) return;
    int pi = i & (SS * DD / 4 - 1);
    float4 p = pe[pi];
    float4 a = qe[i];
    a.x += p.x; a.y += p.y; a.z += p.z; a.w += p.w;
    x[i] = a;
    ((__half2*)(xh + 4 * (size_t)i))[0] = __floats2half2_rn(a.x, a.y);
    ((__half2*)(xh + 4 * (size_t)i))[1] = __floats2half2_rn(a.z, a.w);
    float4 b = qa[i];
    b.x += p.x; b.y += p.y; b.z += p.z; b.w += p.w;
    ((__half2*)(yh + 4 * (size_t)i))[0] = __floats2half2_rn(b.x, b.y);
    ((__half2*)(yh + 4 * (size_t)i))[1] = __floats2half2_rn(b.z, b.w);
}

// ---------------------------------------------------------------------------
// FP16 tensor-core GEMM (R16): 256 threads, BK=32, 3-stage cp.async, ldmatrix.
// MODE 0: fp32 out. MODE 1: ReLU + fp16 out. MODE 2: fp16 out.
// ---------------------------------------------------------------------------
#define HST 40
#define HTILE (128 * HST)
#define STGH (2 * HTILE)
#define NSTG 3
#define GEMM_SMEM (NSTG * STGH * sizeof(__half))   // 61440 B

template<int MODE>
__global__ void __launch_bounds__(256, 2) f16_gemm(
    const __half* __restrict__ A0, const __half* __restrict__ W0,
    const float* __restrict__ b0p, void* __restrict__ C0,
    const __half* __restrict__ A1, const __half* __restrict__ W1p,
    const float* __restrict__ b1p, void* __restrict__ C1,
    int M, int N, int K)
{
    extern __shared__ __half smh[];

    const __half* A    = blockIdx.z ? A1  : A0;
    const __half* W    = blockIdx.z ? W1p : W0;
    const float*  bias = blockIdx.z ? b1p : b0p;
    void*         C    = blockIdx.z ? C1  : C0;

    const int tid  = threadIdx.x;
    const int lane = tid & 31;
    const int wid  = tid >> 5;
    const int wm   = wid & 1;
    const int wn   = wid >> 1;
    const int grp  = lane >> 2;
    const int tig  = lane & 3;
    const int m0   = blockIdx.y * 128;
    const int n0   = blockIdx.x * 128;

    const uint32_t sS = (uint32_t)__cvta_generic_to_shared(smh);

    const int l_row = tid >> 1;
    const int l_h0  = (tid & 1) * 16;

    const uint32_t a_lm = sS + (uint32_t)(((wm * 64 + (lane & 15)) * HST
                                           + ((lane >> 4) << 3)) * 2);
    const uint32_t b_lm = sS + (uint32_t)(HTILE * 2)
                        + (uint32_t)(((wn * 32 + (lane & 7)) * HST
                                           + (((lane >> 3) & 1) << 3)) * 2);

    float acc[4][4][4];
#pragma unroll
    for (int i = 0; i < 4; i++)
#pragma unroll
        for (int j = 0; j < 4; j++)
#pragma unroll
            for (int r = 0; r < 4; r++) acc[i][j][r] = 0.f;

    const int nk = K >> 5;

    auto load_stage = [&](int stg, int k0) {
        const uint32_t sb = sS + (uint32_t)(stg * STGH * 2);
        {
            const __half* ga = A + (size_t)(m0 + l_row) * K + k0 + l_h0;
            uint32_t da = sb + (uint32_t)((l_row * HST + l_h0) * 2);
            cp_async16(da,      ga);
            cp_async16(da + 16, ga + 8);
        }
        {
            const __half* gb = W + (size_t)(n0 + l_row) * K + k0 + l_h0;
            uint32_t db = sb + (uint32_t)((HTILE + l_row * HST + l_h0) * 2);
            cp_async16(db,      gb);
            cp_async16(db + 16, gb + 8);
        }
    };

    load_stage(0, 0);
    cp_commit();
    load_stage(1, 32);
    cp_commit();

    for (int kt = 0; kt < nk; kt++) {
        if (kt + NSTG - 1 < nk) {
            int s = kt + NSTG - 1;
            load_stage(s % NSTG, s * 32);
        }
        cp_commit();
        cp_wait<NSTG - 1>();
        __syncthreads();

        const uint32_t stq = (uint32_t)((kt % NSTG) * STGH * 2);

#pragma unroll
        for (int kk = 0; kk < 32; kk += 16) {
            uint32_t af[4][4];
            uint32_t bf[4][2];
#pragma unroll
            for (int mt = 0; mt < 4; mt++)
                ldsm_x4(af[mt], a_lm + stq + (uint32_t)((mt * 16 * HST + kk) * 2));
#pragma unroll
            for (int nt = 0; nt < 4; nt++)
                ldsm_x2(bf[nt], b_lm + stq + (uint32_t)((nt * 8 * HST + kk) * 2));
#pragma unroll
            for (int mt = 0; mt < 4; mt++)
#pragma unroll
                for (int nt = 0; nt < 4; nt++)
                    mma_f16(acc[mt][nt],
                            af[mt][0], af[mt][1], af[mt][2], af[mt][3],
                            bf[nt][0], bf[nt][1]);
        }
        __syncthreads();
    }

#pragma unroll
    for (int mt = 0; mt < 4; mt++) {
#pragma unroll
        for (int nt = 0; nt < 4; nt++) {
            int row = m0 + wm * 64 + mt * 16 + grp;
            int col = n0 + wn * 32 + nt * 8 + tig * 2;
            float bb0 = bias[col], bb1 = bias[col + 1];
            float v0 = acc[mt][nt][0] + bb0;
            float v1 = acc[mt][nt][1] + bb1;
            float v2 = acc[mt][nt][2] + bb0;
            float v3 = acc[mt][nt][3] + bb1;
            if (MODE == 0) {
                float* Cf = (float*)C;
                *(float2*)(Cf + (size_t)row * N + col)       = make_float2(v0, v1);
                *(float2*)(Cf + (size_t)(row + 8) * N + col) = make_float2(v2, v3);
            } else {
                if (MODE == 1) {
                    v0 = fmaxf(v0, 0.f); v1 = fmaxf(v1, 0.f);
                    v2 = fmaxf(v2, 0.f); v3 = fmaxf(v3, 0.f);
                }
                __half* Ch = (__half*)C;
                *(__half2*)(Ch + (size_t)row * N + col)       = __floats2half2_rn(v0, v1);
                *(__half2*)(Ch + (size_t)(row + 8) * N + col) = __floats2half2_rn(v2, v3);
            }
        }
    }
}

// ---------------------------------------------------------------------------
// FP16 flash attention (R15 pipeline) + ldmatrix fragments everywhere:
// Q via ldsm.x4, K via ldsm.x4 (2 n-tiles/issue), V via ldsm.x4.trans.
// Smem: Qs + 2x Ks + 2x Vs [64][72] halves (46080 B).
// ---------------------------------------------------------------------------
#define APADH 72
#define ATILE (64 * APADH)
#define ATTN_SMEM (5 * ATILE * sizeof(__half))

__global__ void __launch_bounds__(128, 4) attn_f16_kernel(
    const __half* __restrict__ Q, const __half* __restrict__ V,
    const float* __restrict__ FR, __half* __restrict__ AH)
{
    extern __shared__ __half smh[];
    __half* Qs = smh;                        // [64][APADH]

    const int qt   = gridDim.x - 1 - blockIdx.x;   // heavy-first
    const int bh   = blockIdx.y;
    const int b    = bh >> 3;
    const int h    = bh & 7;
    const int tid  = threadIdx.x;
    const int lane = tid & 31;
    const int w    = tid >> 5;
    const int grp  = lane >> 2;
    const int tig  = lane & 3;
    const int q0   = qt * 64;
    const size_t base = (size_t)b * SS * DD + (size_t)h * DKK;

    const uint32_t sB = (uint32_t)__cvta_generic_to_shared(smh);
    const int l_r  = tid >> 3;
    const int l_c8 = (tid & 7) * 8;

    // ldmatrix lane offsets (halves)
    const uint32_t q_lm = sB + (uint32_t)(((w * 16 + (lane & 15)) * APADH
                                           + ((lane >> 4) << 3)) * 2);
    const uint32_t k_lane = (uint32_t)((((lane & 7) + ((lane >> 4) << 3)) * APADH
                                        + (((lane >> 3) & 1) << 3)) * 2);
    const uint32_t v_lane = (uint32_t)((((lane & 7) + (((lane >> 3) & 1) << 3)) * APADH
                                        + ((lane >> 4) << 3)) * 2);

    auto load_kv = [&](int buf, int kt) {
        const uint32_t kb = sB + (uint32_t)((1 + 2 * buf) * ATILE * 2);
        const uint32_t vb = sB + (uint32_t)((2 + 2 * buf) * ATILE * 2);
#pragma unroll
        for (int j = 0; j < 4; j++) {
            int r = l_r + 16 * j;
            const __half* gk = Q + base + (size_t)(kt * 64 + r) * DD + l_c8;
            const __half* gv = V + base + (size_t)(kt * 64 + r) * DD + l_c8;
            uint32_t off = (uint32_t)((r * APADH + l_c8) * 2);
            cp_async16(kb + off, gk);
            cp_async16(vb + off, gv);
        }
    };

#pragma unroll
    for (int j = 0; j < 4; j++) {
        int idx = j * 128 + tid;
        int r   = idx >> 3;
        int c8  = (idx & 7) * 8;
        *(float4*)(Qs + r * APADH + c8) =
            *(const float4*)(Q + base + (size_t)(q0 + r) * DD + c8);
    }

    const int rg0 = q0 + w * 16 + grp;
    const float frs0 = FR[b * SS + rg0]     * 0.125f;
    const float frs1 = FR[b * SS + rg0 + 8] * 0.125f;

    float m0 = -3.0e38f, m1 = -3.0e38f, l0 = 0.f, l1 = 0.f;
    float o[8][4];
#pragma unroll
    for (int nt = 0; nt < 8; nt++)
#pragma unroll
        for (int r = 0; r < 4; r++) o[nt][r] = 0.f;

    load_kv(0, 0);
    cp_commit();

    for (int kt = 0; kt <= qt; kt++) {
        if (kt + 1 <= qt) load_kv((kt + 1) & 1, kt + 1);
        cp_commit();
        cp_wait<1>();
        __syncthreads();

        const uint32_t kbase = sB + (uint32_t)((1 + 2 * (kt & 1)) * ATILE * 2) + k_lane;
        const uint32_t vbase = sB + (uint32_t)((2 + 2 * (kt & 1)) * ATILE * 2) + v_lane;

        // --- S = Q K^T, fragments via ldmatrix ---
        float sc[8][4];
#pragma unroll
        for (int nt = 0; nt < 8; nt++)
#pragma unroll
            for (int r = 0; r < 4; r++) sc[nt][r] = 0.f;

#pragma unroll
        for (int kc = 0; kc < 4; kc++) {
            uint32_t aq[4];
            ldsm_x4(aq, q_lm + (uint32_t)(kc * 32));
#pragma unroll
            for (int p = 0; p < 4; p++) {
                uint32_t kb[4];
                ldsm_x4(kb, kbase + (uint32_t)(p * 16 * APADH * 2 + kc * 32));
                mma_f16(sc[2 * p    ], aq[0], aq[1], aq[2], aq[3], kb[0], kb[1]);
                mma_f16(sc[2 * p + 1], aq[0], aq[1], aq[2], aq[3], kb[2], kb[3]);
            }
        }

        // --- scale + mask + online softmax ---
        const bool diag = (kt == qt);
        float mx0 = -3.0e38f, mx1 = -3.0e38f;
#pragma unroll
        for (int nt = 0; nt < 8; nt++) {
            int cg = kt * 64 + nt * 8 + 2 * tig;
            float s0 = sc[nt][0] * frs0;
            float s1 = sc[nt][1] * frs0;
            float s2 = sc[nt][2] * frs1;
            float s3 = sc[nt][3] * frs1;
            if (diag) {
                if (cg     >= rg0)     s0 = -1e30f;
                if (cg + 1 >= rg0)     s1 = -1e30f;
                if (cg     >= rg0 + 8) s2 = -1e30f;
                if (cg + 1 >= rg0 + 8) s3 = -1e30f;
            }
            sc[nt][0] = s0; sc[nt][1] = s1; sc[nt][2] = s2; sc[nt][3] = s3;
            mx0 = fmaxf(mx0, fmaxf(s0, s1));
            mx1 = fmaxf(mx1, fmaxf(s2, s3));
        }
        mx0 = fmaxf(mx0, __shfl_xor_sync(0xffffffffu, mx0, 1));
        mx0 = fmaxf(mx0, __shfl_xor_sync(0xffffffffu, mx0, 2));
        mx1 = fmaxf(mx1, __shfl_xor_sync(0xffffffffu, mx1, 1));
        mx1 = fmaxf(mx1, __shfl_xor_sync(0xffffffffu, mx1, 2));

        float mn0 = fmaxf(m0, mx0);
        float mn1 = fmaxf(m1, mx1);
        float al0 = __expf(m0 - mn0);
        float al1 = __expf(m1 - mn1);
        m0 = mn0; m1 = mn1;

        float su0 = 0.f, su1 = 0.f;
        uint32_t pu[8][2];
#pragma unroll
        for (int nt = 0; nt < 8; nt++) {
            float p0 = __expf(sc[nt][0] - mn0);
            float p1 = __expf(sc[nt][1] - mn0);
            float p2 = __expf(sc[nt][2] - mn1);
            float p3 = __expf(sc[nt][3] - mn1);
            su0 += p0 + p1;
            su1 += p2 + p3;
            pu[nt][0] = h2u(__floats2half2_rn(p0, p1));
            pu[nt][1] = h2u(__floats2half2_rn(p2, p3));
        }
        su0 += __shfl_xor_sync(0xffffffffu, su0, 1);
        su0 += __shfl_xor_sync(0xffffffffu, su0, 2);
        su1 += __shfl_xor_sync(0xffffffffu, su1, 1);
        su1 += __shfl_xor_sync(0xffffffffu, su1, 2);
        l0 = l0 * al0 + su0;
        l1 = l1 * al1 + su1;
#pragma unroll
        for (int nt = 0; nt < 8; nt++) {
            o[nt][0] *= al0; o[nt][1] *= al0;
            o[nt][2] *= al1; o[nt][3] *= al1;
        }

        // --- O += P V : A-frag = packed C-frag, B via ldsm.x4.trans ---
#pragma unroll
        for (int j = 0; j < 4; j++) {
            uint32_t a0 = pu[2 * j    ][0];
            uint32_t a1 = pu[2 * j    ][1];
            uint32_t a2 = pu[2 * j + 1][0];
            uint32_t a3 = pu[2 * j + 1][1];
#pragma unroll
            for (int p = 0; p < 4; p++) {
                uint32_t vbq[4];
                ldsm_x4t(vbq, vbase + (uint32_t)(j * 16 * APADH * 2 + p * 32));
                mma_f16(o[2 * p    ], a0, a1, a2, a3, vbq[0], vbq[1]);
                mma_f16(o[2 * p + 1], a0, a1, a2, a3, vbq[2], vbq[3]);
            }
        }
        __syncthreads();
    }

    float inv0 = (rg0 == 0) ? 0.f : (1.0f / l0);
    float inv1 = 1.0f / l1;
#pragma unroll
    for (int nt = 0; nt < 8; nt++) {
        int col = nt * 8 + tig * 2;
        *(__half2*)(AH + base + (size_t)(rg0    ) * DD + col) =
            __floats2half2_rn(o[nt][0] * inv0, o[nt][1] * inv0);
        *(__half2*)(AH + base + (size_t)(rg0 + 8) * DD + col) =
            __floats2half2_rn(o[nt][2] * inv1, o[nt][3] * inv1);
    }
}

// ---------------------------------------------------------------------------
// out = LayerNorm(x + r)*g + be; optional fp16 copy outh
// ---------------------------------------------------------------------------
__global__ void __launch_bounds__(128) ln_res_kernel(
    const float* __restrict__ x, const float* __restrict__ r,
    const float* __restrict__ g, const float* __restrict__ be,
    float* __restrict__ out, __half* __restrict__ outh)
{
    int row = blockIdx.x;
    int tid = threadIdx.x;
    const float4* xp = (const float4*)(x + (size_t)row * DD);
    const float4* rp = (const float4*)(r + (size_t)row * DD);
    float4 v = xp[tid], w = rp[tid];
    v.x += w.x; v.y += w.y; v.z += w.z; v.w += w.w;
    float s  = v.x + v.y + v.z + v.w;
    float ss = v.x * v.x + v.y * v.y + v.z * v.z + v.w * v.w;
#pragma unroll
    for (int ofs = 16; ofs > 0; ofs >>= 1) {
        s  += __shfl_xor_sync(0xffffffffu, s,  ofs);
        ss += __shfl_xor_sync(0xffffffffu, ss, ofs);
    }
    __shared__ float sb[4], ssb[4];
    int wid = tid >> 5;
    if ((tid & 31) == 0) { sb[wid] = s; ssb[wid] = ss; }
    __syncthreads();
    s  = sb[0]  + sb[1]  + sb[2]  + sb[3];
    ss = ssb[0] + ssb[1] + ssb[2] + ssb[3];
    float mean = s * (1.0f / DD);
    float var  = ss * (1.0f / DD) - mean * mean;
    float rs   = rsqrtf(var + 1e-5f);
    float4 gv = ((const float4*)g)[tid];
    float4 bv = ((const float4*)be)[tid];
    float4 o4;
    o4.x = (v.x - mean) * rs * gv.x + bv.x;
    o4.y = (v.y - mean) * rs * gv.y + bv.y;
    o4.z = (v.z - mean) * rs * gv.z + bv.z;
    o4.w = (v.w - mean) * rs * gv.w + bv.w;
    ((float4*)(out + (size_t)row * DD))[tid] = o4;
    if (outh) {
        size_t e = (size_t)row * DD + tid * 4;
        ((__half2*)(outh + e))[0] = __floats2half2_rn(o4.x, o4.y);
        ((__half2*)(outh + e))[1] = __floats2half2_rn(o4.z, o4.w);
    }
}

// ---------------------------------------------------------------------------
extern "C" void kernel_launch(void* const* d_in, const int* in_sizes, int n_in,
                              void* d_out, int out_size)
{
    const float* qe  = (const float*)d_in[0];
    const float* qa  = (const float*)d_in[1];
    const float* fr  = (const float*)d_in[2];
    const float* pe  = (const float*)d_in[3];
    const float* Wk  = (const float*)d_in[4];
    const float* bk  = (const float*)d_in[5];
    const float* Wv  = (const float*)d_in[6];
    const float* bv  = (const float*)d_in[7];
    const float* Wo  = (const float*)d_in[8];
    const float* bo  = (const float*)d_in[9];
    const float* g1  = (const float*)d_in[10];
    const float* be1 = (const float*)d_in[11];
    const float* W1  = (const float*)d_in[12];
    const float* bf1 = (const float*)d_in[13];
    const float* W2  = (const float*)d_in[14];
    const float* bf2 = (const float*)d_in[15];
    const float* g2  = (const float*)d_in[16];
    const float* be2 = (const float*)d_in[17];
    float* out = (float*)d_out;

    float  *px, *pt;
    __half *pqh, *pvh, *pxh, *pyh, *pah, *pfh, *pwkt, *pwvt, *pwot, *pw1t, *pw2t;
    cudaGetSymbolAddress((void**)&px,   g_x);
    cudaGetSymbolAddress((void**)&pt,   g_t);
    cudaGetSymbolAddress((void**)&pqh,  g_qh);
    cudaGetSymbolAddress((void**)&pvh,  g_vh);
    cudaGetSymbolAddress((void**)&pxh,  g_xh);
    cudaGetSymbolAddress((void**)&pyh,  g_yh);
    cudaGetSymbolAddress((void**)&pah,  g_ah);
    cudaGetSymbolAddress((void**)&pfh,  g_fh);
    cudaGetSymbolAddress((void**)&pwkt, g_wkt);
    cudaGetSymbolAddress((void**)&pwvt, g_wvt);
    cudaGetSymbolAddress((void**)&pwot, g_wot);
    cudaGetSymbolAddress((void**)&pw1t, g_w1t);
    cudaGetSymbolAddress((void**)&pw2t, g_w2t);

    cudaFuncSetAttribute(attn_f16_kernel,
                         cudaFuncAttributeMaxDynamicSharedMemorySize, (int)ATTN_SMEM);
    cudaFuncSetAttribute(f16_gemm<0>,
                         cudaFuncAttributeMaxDynamicSharedMemorySize, (int)GEMM_SMEM);
    cudaFuncSetAttribute(f16_gemm<1>,
                         cudaFuncAttributeMaxDynamicSharedMemorySize, (int)GEMM_SMEM);
    cudaFuncSetAttribute(f16_gemm<2>,
                         cudaFuncAttributeMaxDynamicSharedMemorySize, (int)GEMM_SMEM);

    wtrans_all_kernel<<<dim3(64, 64, 10), dim3(32, 8)>>>(
        Wk, Wv, Wo, W1, W2, pwkt, pwvt, pwot, pw1t, pw2t);

    add_pe_kernel<<<(BSD / 4 + 255) / 256, 256>>>(
        (const float4*)qe, (const float4*)qa, (const float4*)pe,
        (float4*)px, pxh, pyh);

    dim3 g512 (DD / 128, MTOK / 128, 1);   // (4, 128)
    dim3 g512z(DD / 128, MTOK / 128, 2);   // merged q & v
    dim3 gff  (FFD / 128, MTOK / 128, 1);  // (16, 128)
    dim3 gattn(SS / 64, BB * HH);          // (8, 256)

    for (int i = 0; i < NBLK; i++) {
        const __half* wkt = pwkt + (size_t)i * DD * DD;
        const __half* wvt = pwvt + (size_t)i * DD * DD;
        const __half* wot = pwot + (size_t)i * DD * DD;
        const __half* w1t = pw1t + (size_t)i * DD * FFD;
        const __half* w2t = pw2t + (size_t)i * FFD * DD;

        // merged: z=0 -> q = x@Wk + bk (fp16) ; z=1 -> v = y@Wv + bv (fp16)
        f16_gemm<2><<<g512z, 256, GEMM_SMEM>>>(
            pxh, wkt, bk + i * DD, pqh,
            pyh, wvt, bv + i * DD, pvh, MTOK, DD, DD);
        // attention (fp16 in/out)
        attn_f16_kernel<<<gattn, 128, ATTN_SMEM>>>(pqh, pvh, fr, pah);
        // proj = ah @ Wo + bo -> pt (fp32)
        f16_gemm<0><<<g512, 256, GEMM_SMEM>>>(
            pah, wot, bo + i * DD, pt,
            pah, wot, bo + i * DD, pt, MTOK, DD, DD);
        // x = LN(x + proj); xh = fp16(x)
        ln_res_kernel<<<MTOK, 128>>>(px, pt, g1 + i * DD, be1 + i * DD, px, pxh);
        // hidden = relu(x @ W1 + bf1) -> fp16 fh
        f16_gemm<1><<<gff, 256, GEMM_SMEM>>>(
            pxh, w1t, bf1 + i * FFD, pfh,
            pxh, w1t, bf1 + i * FFD, pfh, MTOK, FFD, DD);
        // ffn = fh @ W2 + bf2 -> pt (fp32)
        f16_gemm<0><<<g512, 256, GEMM_SMEM>>>(
            pfh, w2t, bf2 + i * DD, pt,
            pfh, w2t, bf2 + i * DD, pt, MTOK, DD, FFD);
        // x = LN(x + ffn)
        float*  dst = (i == NBLK - 1) ? out : px;
        __half* dh  = (i == NBLK - 1) ? nullptr : pxh;
        ln_res_kernel<<<MTOK, 128>>>(px, pt, g2 + i * DD, be2 + i * DD, dst, dh);
    }
}